// round 3
// baseline (speedup 1.0000x reference)
#include <cuda_runtime.h>
#include <cuda_bf16.h>

#define NN 100000
#define NE 1600000
#define NG 512
#define DIM 128
#define NC 10
#define SCAN_B 1024
#define NBLK ((NN + SCAN_B - 1) / SCAN_B)

typedef unsigned long long ull;

// packed f32x2 FMA: d = a*b + c (elementwise on packed pairs)
#define FMA_F32X2(d, a, b, c) \
    asm("fma.rn.f32x2 %0, %1, %2, %3;" : "=l"(d) : "l"(a), "l"(b), "l"(c))
#define PACK_F32X2(out, lo, hi) \
    asm("mov.b64 %0, {%1, %2};" : "=l"(out) : "f"(lo), "f"(hi))

// ---------------- scratch (device globals: allocation-free rule) --------------
__device__ int   g_is64;              // 1 if index inputs are int64, 0 if int32
__device__ int   g_deg[NN];
__device__ float g_dinv[NN];
__device__ int   g_off[NN + 1];
__device__ int   g_pos[NN];
__device__ int   g_src[NE];
__device__ int   g_bsum[NBLK];
__device__ float g_xw[(size_t)NN * DIM];   // GEMM output (per layer)
__device__ float g_h[(size_t)NN * DIM];    // aggregation output (per layer)
__device__ float g_pool[NG * DIM];
__device__ float g_cnt[NG];

__device__ __forceinline__ int idx_at(const void* p, long long i, int is64) {
    return is64 ? (int)((const long long*)p)[i] : ((const int*)p)[i];
}

// ---------------- dtype probe -------------------------------------------------
__global__ void k_probe(const void* ei) {
    if (threadIdx.x == 0 && blockIdx.x == 0) {
        const int* w = (const int*)ei;
        int nz = 0;
        for (int i = 0; i < 128; ++i) nz += (w[2 * i + 1] != 0);
        g_is64 = (nz == 0) ? 1 : 0;
    }
}

// ---------------- setup kernels ----------------------------------------------
__global__ void k_zero() {
    int i = blockIdx.x * blockDim.x + threadIdx.x;
    int stride = gridDim.x * blockDim.x;
    for (int j = i; j < NN; j += stride) g_deg[j] = 0;
    for (int j = i; j < NG * DIM; j += stride) g_pool[j] = 0.f;
    for (int j = i; j < NG; j += stride) g_cnt[j] = 0.f;
}

// in-degree histogram + per-graph node counts (merged)
__global__ void k_hist(const void* __restrict__ ei, const void* __restrict__ batch) {
    int i = blockIdx.x * blockDim.x + threadIdx.x;
    int stride = gridDim.x * blockDim.x;
    int is64 = g_is64;
    for (int e = i; e < NE; e += stride) {
        int d = idx_at(ei, (long long)NE + e, is64);
        atomicAdd(&g_deg[d], 1);
    }
    for (int j = i; j < NN; j += stride)
        atomicAdd(&g_cnt[idx_at(batch, j, is64)], 1.f);
}

// block-level exclusive scan of g_deg -> g_off (partial); also computes dinv
__global__ void k_scan_local() {
    __shared__ int s[SCAN_B];
    int t = threadIdx.x;
    int idx = blockIdx.x * SCAN_B + t;
    int v = (idx < NN) ? g_deg[idx] : 0;
    if (idx < NN) g_dinv[idx] = rsqrtf((float)(v + 1));
    s[t] = v;
    __syncthreads();
    for (int d = 1; d < SCAN_B; d <<= 1) {
        int x = (t >= d) ? s[t - d] : 0;
        __syncthreads();
        s[t] += x;
        __syncthreads();
    }
    if (idx < NN) g_off[idx] = s[t] - v;     // exclusive
    if (t == SCAN_B - 1) g_bsum[blockIdx.x] = s[t];
}

__global__ void k_scan_blocks() {
    if (threadIdx.x == 0 && blockIdx.x == 0) {
        int run = 0;
        for (int b = 0; b < NBLK; ++b) { int v = g_bsum[b]; g_bsum[b] = run; run += v; }
    }
}

__global__ void k_scan_add() {
    int idx = blockIdx.x * blockDim.x + threadIdx.x;
    if (idx < NN) {
        int o = g_off[idx] + g_bsum[idx / SCAN_B];
        g_off[idx] = o;
        g_pos[idx] = o;
    }
    if (idx == 0) g_off[NN] = NE;
}

__global__ void k_csr(const void* __restrict__ ei) {
    int i = blockIdx.x * blockDim.x + threadIdx.x;
    int stride = gridDim.x * blockDim.x;
    int is64 = g_is64;
    for (int e = i; e < NE; e += stride) {
        int s = idx_at(ei, e, is64);
        int d = idx_at(ei, (long long)NE + e, is64);
        int p = atomicAdd(&g_pos[d], 1);
        g_src[p] = s;
    }
}

// ---------------- SGEMM via packed fma.rn.f32x2 ------------------------------
// g_xw[n,128] = A[n,128] @ W[128,128]
// Block tile: 64 rows x 128 cols, 256 threads, each thread 4 rows x 8 cols
// (held as 4 col-pairs). A staged in smem pre-duplicated as (a,a) packs.
#define GR 64
#define GT 256
__global__ __launch_bounds__(GT) void k_gemm(const float* __restrict__ Aext,
                                             const float* __restrict__ W,
                                             int a_is_h, int n) {
    const float* A = a_is_h ? g_h : Aext;
    float* O = g_xw;
    __shared__ ull   xs2[32][GR];      // packed (a,a): 16 KB
    __shared__ float ws[32][128];      // [k][col]:     16 KB

    int tid = threadIdx.x;
    int row0 = blockIdx.x * GR;
    int ty = tid >> 4;                 // 0..15 -> rows ty*4..ty*4+3
    int tx = tid & 15;                 // 0..15 -> cols tx*8..tx*8+7

    ull acc[4][4];
#pragma unroll
    for (int i = 0; i < 4; ++i)
#pragma unroll
        for (int j = 0; j < 4; ++j) acc[i][j] = 0ull;

    for (int k0 = 0; k0 < 128; k0 += 32) {
        // stage A tile duplicated: 64 rows x 32 k
        {
            int r = tid >> 2;              // 0..63
            int kq = (tid & 3) * 8;        // 0,8,16,24
            int grow = row0 + r;
            float v[8];
            if (grow < n) {
                *(float4*)&v[0] = *(const float4*)&A[(size_t)grow * 128 + k0 + kq];
                *(float4*)&v[4] = *(const float4*)&A[(size_t)grow * 128 + k0 + kq + 4];
            } else {
#pragma unroll
                for (int m = 0; m < 8; ++m) v[m] = 0.f;
            }
#pragma unroll
            for (int m = 0; m < 8; ++m) {
                ull p;
                PACK_F32X2(p, v[m], v[m]);
                xs2[kq + m][r] = p;
            }
        }
        // stage W tile: 32 k x 128 cols
#pragma unroll
        for (int p = 0; p < 4; ++p) {
            int lin = p * 1024 + tid * 4;
            int kk = lin >> 7, cc = lin & 127;
            *(float4*)&ws[kk][cc] = *(const float4*)&W[(size_t)(k0 + kk) * 128 + cc];
        }
        __syncthreads();
#pragma unroll
        for (int k = 0; k < 32; ++k) {
            ulonglong2 b01 = *(const ulonglong2*)&ws[k][tx * 8];
            ulonglong2 b23 = *(const ulonglong2*)&ws[k][tx * 8 + 4];
#pragma unroll
            for (int i = 0; i < 4; ++i) {
                ull a = xs2[k][ty * 4 + i];
                FMA_F32X2(acc[i][0], a, b01.x, acc[i][0]);
                FMA_F32X2(acc[i][1], a, b01.y, acc[i][1]);
                FMA_F32X2(acc[i][2], a, b23.x, acc[i][2]);
                FMA_F32X2(acc[i][3], a, b23.y, acc[i][3]);
            }
        }
        __syncthreads();
    }
#pragma unroll
    for (int i = 0; i < 4; ++i) {
        int grow = row0 + ty * 4 + i;
        if (grow < n) {
            ulonglong2 s0, s1;
            s0.x = acc[i][0]; s0.y = acc[i][1];
            s1.x = acc[i][2]; s1.y = acc[i][3];
            *(ulonglong2*)&O[(size_t)grow * 128 + tx * 8]     = s0;
            *(ulonglong2*)&O[(size_t)grow * 128 + tx * 8 + 4] = s1;
        }
    }
}

// ---------------- aggregation: one warp per destination node -----------------
// g_h[d] = dinv[d]*( g_xw[d]*dinv[d] + sum_{e: dst=d} g_xw[src]*dinv[src] ) + bias
__global__ void k_agg(const float* __restrict__ bias, int dorelu) {
    int warp = (blockIdx.x * blockDim.x + threadIdx.x) >> 5;
    if (warp >= NN) return;
    int lane = threadIdx.x & 31;
    float di = g_dinv[warp];
    const float4* xw4 = (const float4*)g_xw;

    float4 v0 = xw4[(size_t)warp * 32 + lane];
    float4 acc = make_float4(v0.x * di, v0.y * di, v0.z * di, v0.w * di);

    int e0 = g_off[warp], e1 = g_off[warp + 1];
    int e = e0;
    // full 32-edge chunks (unrolled for load pipelining)
    for (; e + 32 <= e1; e += 32) {
        int sidx = g_src[e + lane];
        float dv = g_dinv[sidx];
#pragma unroll 4
        for (int j = 0; j < 32; ++j) {
            int s = __shfl_sync(0xffffffffu, sidx, j);
            float w = __shfl_sync(0xffffffffu, dv, j);
            float4 v = xw4[(size_t)s * 32 + lane];
            acc.x += v.x * w;
            acc.y += v.y * w;
            acc.z += v.z * w;
            acc.w += v.w * w;
        }
    }
    if (e < e1) {
        int cnt = e1 - e;
        int sidx = (lane < cnt) ? g_src[e + lane] : 0;
        float dv = (lane < cnt) ? g_dinv[sidx] : 0.f;
        for (int j = 0; j < cnt; ++j) {
            int s = __shfl_sync(0xffffffffu, sidx, j);
            float w = __shfl_sync(0xffffffffu, dv, j);
            float4 v = xw4[(size_t)s * 32 + lane];
            acc.x += v.x * w;
            acc.y += v.y * w;
            acc.z += v.z * w;
            acc.w += v.w * w;
        }
    }
    float4 bb = ((const float4*)bias)[lane];
    acc.x = acc.x * di + bb.x;
    acc.y = acc.y * di + bb.y;
    acc.z = acc.z * di + bb.z;
    acc.w = acc.w * di + bb.w;
    if (dorelu) {
        acc.x = fmaxf(acc.x, 0.f);
        acc.y = fmaxf(acc.y, 0.f);
        acc.z = fmaxf(acc.z, 0.f);
        acc.w = fmaxf(acc.w, 0.f);
    }
    ((float4*)g_h)[(size_t)warp * 32 + lane] = acc;
}

// ---------------- pooling ------------------------------------------------------
#define PNODES 256
__global__ void k_pool(const void* __restrict__ batch) {
    int t = threadIdx.x;               // feature 0..127
    int start = blockIdx.x * PNODES;
    int end = min(start + PNODES, NN);
    if (start >= NN) return;
    int is64 = g_is64;
    float acc = 0.f;
    int gprev = idx_at(batch, start, is64);
    for (int i = start; i < end; ++i) {
        int g = idx_at(batch, i, is64);
        if (g != gprev) {
            atomicAdd(&g_pool[gprev * DIM + t], acc);
            acc = 0.f;
            gprev = g;
        }
        acc += g_h[(size_t)i * DIM + t];
    }
    atomicAdd(&g_pool[gprev * DIM + t], acc);
}

__global__ void k_final(const float* __restrict__ Wc, const float* __restrict__ bc,
                        float* __restrict__ out) {
    __shared__ float gs[DIM];
    int b = blockIdx.x, t = threadIdx.x;
    float c = fmaxf(g_cnt[b], 1.f);
    gs[t] = g_pool[b * DIM + t] / c;
    __syncthreads();
    if (t < NC) {
        float s = bc[t];
#pragma unroll 16
        for (int k = 0; k < DIM; ++k) s += gs[k] * Wc[k * NC + t];
        out[b * NC + t] = s;
    }
}

// ---------------- launch -------------------------------------------------------
extern "C" void kernel_launch(void* const* d_in, const int* in_sizes, int n_in,
                              void* d_out, int out_size) {
    const float* x     = (const float*)d_in[0];
    const void*  ei    = d_in[1];
    const void*  batch = d_in[2];
    const float* W1    = (const float*)d_in[3];
    const float* b1    = (const float*)d_in[4];
    const float* W2    = (const float*)d_in[5];
    const float* b2    = (const float*)d_in[6];
    const float* Wc    = (const float*)d_in[7];
    const float* bc    = (const float*)d_in[8];
    float*       out   = (float*)d_out;

    k_probe<<<1, 32>>>(ei);
    k_zero<<<256, 256>>>();
    k_hist<<<512, 256>>>(ei, batch);
    k_scan_local<<<NBLK, SCAN_B>>>();
    k_scan_blocks<<<1, 32>>>();
    k_scan_add<<<(NN + 255) / 256, 256>>>();
    k_csr<<<512, 256>>>(ei);

    int gemm_blocks = (NN + GR - 1) / GR;
    int agg_blocks = (NN * 32 + 255) / 256;

    // layer 1
    k_gemm<<<gemm_blocks, GT>>>(x, W1, 0, NN);
    k_agg<<<agg_blocks, 256>>>(b1, 1);
    // layer 2
    k_gemm<<<gemm_blocks, GT>>>(nullptr, W2, 1, NN);
    k_agg<<<agg_blocks, 256>>>(b2, 0);
    // pooling + classifier
    k_pool<<<(NN + PNODES - 1) / PNODES, DIM>>>(batch);
    k_final<<<NG, DIM>>>(Wc, bc, out);
}

// round 4
// speedup vs baseline: 1.1392x; 1.1392x over previous
#include <cuda_runtime.h>
#include <cuda_bf16.h>
#include <cstdint>

#define NN 100000
#define NE 1600000
#define NG 512
#define DIM 128
#define NC 10
#define SCAN_B 1024
#define NBLK ((NN + SCAN_B - 1) / SCAN_B)

// ---------------- scratch (device globals: allocation-free rule) --------------
__device__ int   g_is64;
__device__ int   g_deg[NN];
__device__ float g_dinv[NN];
__device__ int   g_off[NN + 1];
__device__ int   g_pos[NN];
__device__ int   g_src[NE];
__device__ int   g_bsum[NBLK];
__device__ float g_xw[(size_t)NN * DIM];
__device__ float g_h[(size_t)NN * DIM];
__device__ float g_pool[NG * DIM];
__device__ float g_cnt[NG];

__device__ __forceinline__ int idx_at(const void* p, long long i, int is64) {
    return is64 ? (int)((const long long*)p)[i] : ((const int*)p)[i];
}

// split v into tf32 hi + tf32 lo  (3xTF32 trick)
__device__ __forceinline__ float2 split_tf32(float v) {
    unsigned hi_b, lo_b;
    asm("cvt.rna.tf32.f32 %0, %1;" : "=r"(hi_b) : "f"(v));
    float hif = __uint_as_float(hi_b);
    float lo = v - hif;
    asm("cvt.rna.tf32.f32 %0, %1;" : "=r"(lo_b) : "f"(lo));
    return make_float2(hif, __uint_as_float(lo_b));
}

#define MMA_TF32(d, a0, a1, a2, a3, b0, b1)                                         \
    asm volatile("mma.sync.aligned.m16n8k8.row.col.f32.tf32.tf32.f32 "              \
                 "{%0,%1,%2,%3},{%4,%5,%6,%7},{%8,%9},{%0,%1,%2,%3};"               \
                 : "+f"(d[0]), "+f"(d[1]), "+f"(d[2]), "+f"(d[3])                    \
                 : "r"(a0), "r"(a1), "r"(a2), "r"(a3), "r"(b0), "r"(b1))

// ---------------- dtype probe -------------------------------------------------
__global__ void k_probe(const void* ei) {
    if (threadIdx.x == 0 && blockIdx.x == 0) {
        const int* w = (const int*)ei;
        int nz = 0;
        for (int i = 0; i < 128; ++i) nz += (w[2 * i + 1] != 0);
        g_is64 = (nz == 0) ? 1 : 0;
    }
}

// ---------------- setup kernels ----------------------------------------------
__global__ void k_zero() {
    int i = blockIdx.x * blockDim.x + threadIdx.x;
    int stride = gridDim.x * blockDim.x;
    for (int j = i; j < NN; j += stride) g_deg[j] = 0;
    for (int j = i; j < NG * DIM; j += stride) g_pool[j] = 0.f;
    for (int j = i; j < NG; j += stride) g_cnt[j] = 0.f;
}

__global__ void k_hist(const void* __restrict__ ei, const void* __restrict__ batch) {
    int i = blockIdx.x * blockDim.x + threadIdx.x;
    int stride = gridDim.x * blockDim.x;
    int is64 = g_is64;
    for (int e = i; e < NE; e += stride) {
        int d = idx_at(ei, (long long)NE + e, is64);
        atomicAdd(&g_deg[d], 1);
    }
    for (int j = i; j < NN; j += stride)
        atomicAdd(&g_cnt[idx_at(batch, j, is64)], 1.f);
}

__global__ void k_scan_local() {
    __shared__ int s[SCAN_B];
    int t = threadIdx.x;
    int idx = blockIdx.x * SCAN_B + t;
    int v = (idx < NN) ? g_deg[idx] : 0;
    if (idx < NN) g_dinv[idx] = rsqrtf((float)(v + 1));
    s[t] = v;
    __syncthreads();
    for (int d = 1; d < SCAN_B; d <<= 1) {
        int x = (t >= d) ? s[t - d] : 0;
        __syncthreads();
        s[t] += x;
        __syncthreads();
    }
    if (idx < NN) g_off[idx] = s[t] - v;
    if (t == SCAN_B - 1) g_bsum[blockIdx.x] = s[t];
}

__global__ void k_scan_blocks() {
    if (threadIdx.x == 0 && blockIdx.x == 0) {
        int run = 0;
        for (int b = 0; b < NBLK; ++b) { int v = g_bsum[b]; g_bsum[b] = run; run += v; }
    }
}

__global__ void k_scan_add() {
    int idx = blockIdx.x * blockDim.x + threadIdx.x;
    if (idx < NN) {
        int o = g_off[idx] + g_bsum[idx / SCAN_B];
        g_off[idx] = o;
        g_pos[idx] = o;
    }
    if (idx == 0) g_off[NN] = NE;
}

__global__ void k_csr(const void* __restrict__ ei) {
    int i = blockIdx.x * blockDim.x + threadIdx.x;
    int stride = gridDim.x * blockDim.x;
    int is64 = g_is64;
    for (int e = i; e < NE; e += stride) {
        int s = idx_at(ei, e, is64);
        int d = idx_at(ei, (long long)NE + e, is64);
        int p = atomicAdd(&g_pos[d], 1);
        g_src[p] = s;
    }
}

// ---------------- 3xTF32 tensor-core GEMM ------------------------------------
// g_xw[n,128] = A[n,128] @ W[128,128]
// 256 threads (8 warps), tile 128 rows x 128 cols, K in 16-wide panels.
// Each warp: 16 rows x 128 cols via m16n8k8 MMAs (16 n-tiles), 3 MMAs per
// (n-tile, k8) for the hi/lo split.
#define MB 128
__global__ __launch_bounds__(256) void k_gemm_tc(const float* __restrict__ Aext,
                                                 const float* __restrict__ W,
                                                 int a_is_h, int n) {
    const float* A = a_is_h ? g_h : Aext;
    __shared__ float2 As2[MB][17];     // [row][k]  (hi,lo) pairs, padded
    __shared__ float2 Ws2[16][130];    // [k][col]  (hi,lo) pairs, padded

    int tid = threadIdx.x;
    int row0 = blockIdx.x * MB;
    int lane = tid & 31, wid = tid >> 5;
    int wr = wid * 16;                 // warp row offset in tile
    int g = lane >> 2, tg = lane & 3;  // groupID, threadID-in-group

    float acc[16][4];
#pragma unroll
    for (int j = 0; j < 16; ++j)
#pragma unroll
        for (int q = 0; q < 4; ++q) acc[j][q] = 0.f;

    for (int k0 = 0; k0 < 128; k0 += 16) {
        // stage A panel: 128 rows x 16 k
#pragma unroll
        for (int it = 0; it < 2; ++it) {
            int idx = it * 256 + tid;          // 0..511
            int r = idx >> 2;
            int kq = (idx & 3) * 4;
            float4 v = make_float4(0.f, 0.f, 0.f, 0.f);
            if (row0 + r < n)
                v = *(const float4*)&A[(size_t)(row0 + r) * 128 + k0 + kq];
            As2[r][kq + 0] = split_tf32(v.x);
            As2[r][kq + 1] = split_tf32(v.y);
            As2[r][kq + 2] = split_tf32(v.z);
            As2[r][kq + 3] = split_tf32(v.w);
        }
        // stage W panel: 16 k x 128 cols
#pragma unroll
        for (int it = 0; it < 2; ++it) {
            int idx = it * 256 + tid;
            int kk = idx >> 5;                 // 0..15
            int cc = (idx & 31) * 4;
            float4 v = *(const float4*)&W[(size_t)(k0 + kk) * 128 + cc];
            Ws2[kk][cc + 0] = split_tf32(v.x);
            Ws2[kk][cc + 1] = split_tf32(v.y);
            Ws2[kk][cc + 2] = split_tf32(v.z);
            Ws2[kk][cc + 3] = split_tf32(v.w);
        }
        __syncthreads();
#pragma unroll
        for (int ks = 0; ks < 2; ++ks) {
            int k8 = ks * 8;
            float2 fa0 = As2[wr + g][k8 + tg];
            float2 fa1 = As2[wr + g + 8][k8 + tg];
            float2 fa2 = As2[wr + g][k8 + tg + 4];
            float2 fa3 = As2[wr + g + 8][k8 + tg + 4];
            unsigned ah0 = __float_as_uint(fa0.x), al0 = __float_as_uint(fa0.y);
            unsigned ah1 = __float_as_uint(fa1.x), al1 = __float_as_uint(fa1.y);
            unsigned ah2 = __float_as_uint(fa2.x), al2 = __float_as_uint(fa2.y);
            unsigned ah3 = __float_as_uint(fa3.x), al3 = __float_as_uint(fa3.y);
#pragma unroll
            for (int j = 0; j < 16; ++j) {
                float2 fb0 = Ws2[k8 + tg][j * 8 + g];
                float2 fb1 = Ws2[k8 + tg + 4][j * 8 + g];
                unsigned bh0 = __float_as_uint(fb0.x), bl0 = __float_as_uint(fb0.y);
                unsigned bh1 = __float_as_uint(fb1.x), bl1 = __float_as_uint(fb1.y);
                MMA_TF32(acc[j], ah0, ah1, ah2, ah3, bh0, bh1);
                MMA_TF32(acc[j], ah0, ah1, ah2, ah3, bl0, bl1);
                MMA_TF32(acc[j], al0, al1, al2, al3, bh0, bh1);
            }
        }
        __syncthreads();
    }
    // epilogue
    int r0 = row0 + wr + g;
#pragma unroll
    for (int j = 0; j < 16; ++j) {
        int c = j * 8 + 2 * tg;
        if (r0 < n)
            *(float2*)&g_xw[(size_t)r0 * 128 + c] = make_float2(acc[j][0], acc[j][1]);
        if (r0 + 8 < n)
            *(float2*)&g_xw[(size_t)(r0 + 8) * 128 + c] = make_float2(acc[j][2], acc[j][3]);
    }
}

// ---------------- aggregation: one warp per destination node -----------------
__global__ void k_agg(const float* __restrict__ bias, int dorelu) {
    int warp = (blockIdx.x * blockDim.x + threadIdx.x) >> 5;
    if (warp >= NN) return;
    int lane = threadIdx.x & 31;
    float di = g_dinv[warp];
    const float4* xw4 = (const float4*)g_xw;

    float4 v0 = xw4[(size_t)warp * 32 + lane];
    float4 acc = make_float4(v0.x * di, v0.y * di, v0.z * di, v0.w * di);

    int e0 = g_off[warp], e1 = g_off[warp + 1];
    for (int e = e0; e < e1; e += 32) {
        int cnt = min(32, e1 - e);
        int sidx = (lane < cnt) ? g_src[e + lane] : 0;
        float dv = (lane < cnt) ? g_dinv[sidx] : 0.f;
        for (int j = 0; j < cnt; ++j) {
            int s = __shfl_sync(0xffffffffu, sidx, j);
            float w = __shfl_sync(0xffffffffu, dv, j);
            float4 v = xw4[(size_t)s * 32 + lane];
            acc.x += v.x * w;
            acc.y += v.y * w;
            acc.z += v.z * w;
            acc.w += v.w * w;
        }
    }
    float4 bb = ((const float4*)bias)[lane];
    acc.x = acc.x * di + bb.x;
    acc.y = acc.y * di + bb.y;
    acc.z = acc.z * di + bb.z;
    acc.w = acc.w * di + bb.w;
    if (dorelu) {
        acc.x = fmaxf(acc.x, 0.f);
        acc.y = fmaxf(acc.y, 0.f);
        acc.z = fmaxf(acc.z, 0.f);
        acc.w = fmaxf(acc.w, 0.f);
    }
    ((float4*)g_h)[(size_t)warp * 32 + lane] = acc;
}

// ---------------- pooling ------------------------------------------------------
#define PNODES 256
__global__ void k_pool(const void* __restrict__ batch) {
    int t = threadIdx.x;
    int start = blockIdx.x * PNODES;
    int end = min(start + PNODES, NN);
    if (start >= NN) return;
    int is64 = g_is64;
    float acc = 0.f;
    int gprev = idx_at(batch, start, is64);
    for (int i = start; i < end; ++i) {
        int gq = idx_at(batch, i, is64);
        if (gq != gprev) {
            atomicAdd(&g_pool[gprev * DIM + t], acc);
            acc = 0.f;
            gprev = gq;
        }
        acc += g_h[(size_t)i * DIM + t];
    }
    atomicAdd(&g_pool[gprev * DIM + t], acc);
}

__global__ void k_final(const float* __restrict__ Wc, const float* __restrict__ bc,
                        float* __restrict__ out) {
    __shared__ float gs[DIM];
    int b = blockIdx.x, t = threadIdx.x;
    float c = fmaxf(g_cnt[b], 1.f);
    gs[t] = g_pool[b * DIM + t] / c;
    __syncthreads();
    if (t < NC) {
        float s = bc[t];
#pragma unroll 16
        for (int k = 0; k < DIM; ++k) s += gs[k] * Wc[k * NC + t];
        out[b * NC + t] = s;
    }
}

// ---------------- launch -------------------------------------------------------
extern "C" void kernel_launch(void* const* d_in, const int* in_sizes, int n_in,
                              void* d_out, int out_size) {
    const float* x     = (const float*)d_in[0];
    const void*  ei    = d_in[1];
    const void*  batch = d_in[2];
    const float* W1    = (const float*)d_in[3];
    const float* b1    = (const float*)d_in[4];
    const float* W2    = (const float*)d_in[5];
    const float* b2    = (const float*)d_in[6];
    const float* Wc    = (const float*)d_in[7];
    const float* bc    = (const float*)d_in[8];
    float*       out   = (float*)d_out;

    k_probe<<<1, 32>>>(ei);
    k_zero<<<256, 256>>>();
    k_hist<<<512, 256>>>(ei, batch);
    k_scan_local<<<NBLK, SCAN_B>>>();
    k_scan_blocks<<<1, 32>>>();
    k_scan_add<<<(NN + 255) / 256, 256>>>();
    k_csr<<<512, 256>>>(ei);

    int gemm_blocks = (NN + MB - 1) / MB;
    int agg_blocks = (NN * 32 + 255) / 256;

    // layer 1
    k_gemm_tc<<<gemm_blocks, 256>>>(x, W1, 0, NN);
    k_agg<<<agg_blocks, 256>>>(b1, 1);
    // layer 2
    k_gemm_tc<<<gemm_blocks, 256>>>(nullptr, W2, 1, NN);
    k_agg<<<agg_blocks, 256>>>(b2, 0);
    // pooling + classifier
    k_pool<<<(NN + PNODES - 1) / PNODES, DIM>>>(batch);
    k_final<<<NG, DIM>>>(Wc, bc, out);
}

// round 5
// speedup vs baseline: 1.1516x; 1.0108x over previous
#include <cuda_runtime.h>
#include <cuda_bf16.h>
#include <cstdint>

#define NN 100000
#define NE 1600000
#define NG 512
#define DIM 128
#define NC 10
#define SCAN_B 1024
#define NBLK ((NN + SCAN_B - 1) / SCAN_B)

// ---------------- scratch (device globals: allocation-free rule) --------------
__device__ int   g_is64;
__device__ int   g_deg[NN];
__device__ float g_dinv[NN];
__device__ int   g_off[NN + 1];
__device__ int   g_pos[NN];
__device__ int   g_src[NE];
__device__ int   g_bsum[NBLK];
__device__ float g_xw[(size_t)NN * DIM];
__device__ float g_h[(size_t)NN * DIM];
__device__ float g_pool[NG * DIM];
__device__ float g_cnt[NG];

__device__ __forceinline__ int idx_at(const void* p, long long i, int is64) {
    return is64 ? (int)((const long long*)p)[i] : ((const int*)p)[i];
}

// split v into tf32 hi + tf32 lo  (3xTF32 trick)
__device__ __forceinline__ float2 split_tf32(float v) {
    unsigned hi_b, lo_b;
    asm("cvt.rna.tf32.f32 %0, %1;" : "=r"(hi_b) : "f"(v));
    float hif = __uint_as_float(hi_b);
    float lo = v - hif;
    asm("cvt.rna.tf32.f32 %0, %1;" : "=r"(lo_b) : "f"(lo));
    return make_float2(hif, __uint_as_float(lo_b));
}

#define MMA_TF32(d, a0, a1, a2, a3, b0, b1)                                         \
    asm volatile("mma.sync.aligned.m16n8k8.row.col.f32.tf32.tf32.f32 "              \
                 "{%0,%1,%2,%3},{%4,%5,%6,%7},{%8,%9},{%0,%1,%2,%3};"               \
                 : "+f"(d[0]), "+f"(d[1]), "+f"(d[2]), "+f"(d[3])                    \
                 : "r"(a0), "r"(a1), "r"(a2), "r"(a3), "r"(b0), "r"(b1))

// ---------------- dtype probe -------------------------------------------------
__global__ void k_probe(const void* ei) {
    if (threadIdx.x == 0 && blockIdx.x == 0) {
        const int* w = (const int*)ei;
        int nz = 0;
        for (int i = 0; i < 128; ++i) nz += (w[2 * i + 1] != 0);
        g_is64 = (nz == 0) ? 1 : 0;
    }
}

// ---------------- setup kernels ----------------------------------------------
__global__ void k_zero() {
    int i = blockIdx.x * blockDim.x + threadIdx.x;
    int stride = gridDim.x * blockDim.x;
    for (int j = i; j < NN; j += stride) g_deg[j] = 0;
    for (int j = i; j < NG * DIM; j += stride) g_pool[j] = 0.f;
    for (int j = i; j < NG; j += stride) g_cnt[j] = 0.f;
}

__global__ void k_hist(const void* __restrict__ ei, const void* __restrict__ batch) {
    int i = blockIdx.x * blockDim.x + threadIdx.x;
    int stride = gridDim.x * blockDim.x;
    int is64 = g_is64;
    for (int e = i; e < NE; e += stride) {
        int d = idx_at(ei, (long long)NE + e, is64);
        atomicAdd(&g_deg[d], 1);
    }
    for (int j = i; j < NN; j += stride)
        atomicAdd(&g_cnt[idx_at(batch, j, is64)], 1.f);
}

__global__ void k_scan_local() {
    __shared__ int s[SCAN_B];
    int t = threadIdx.x;
    int idx = blockIdx.x * SCAN_B + t;
    int v = (idx < NN) ? g_deg[idx] : 0;
    if (idx < NN) g_dinv[idx] = rsqrtf((float)(v + 1));
    s[t] = v;
    __syncthreads();
    for (int d = 1; d < SCAN_B; d <<= 1) {
        int x = (t >= d) ? s[t - d] : 0;
        __syncthreads();
        s[t] += x;
        __syncthreads();
    }
    if (idx < NN) g_off[idx] = s[t] - v;
    if (t == SCAN_B - 1) g_bsum[blockIdx.x] = s[t];
}

__global__ void k_scan_blocks() {
    if (threadIdx.x == 0 && blockIdx.x == 0) {
        int run = 0;
        for (int b = 0; b < NBLK; ++b) { int v = g_bsum[b]; g_bsum[b] = run; run += v; }
    }
}

__global__ void k_scan_add() {
    int idx = blockIdx.x * blockDim.x + threadIdx.x;
    if (idx < NN) {
        int o = g_off[idx] + g_bsum[idx / SCAN_B];
        g_off[idx] = o;
        g_pos[idx] = o;
    }
    if (idx == 0) g_off[NN] = NE;
}

__global__ void k_csr(const void* __restrict__ ei) {
    int i = blockIdx.x * blockDim.x + threadIdx.x;
    int stride = gridDim.x * blockDim.x;
    int is64 = g_is64;
    for (int e = i; e < NE; e += stride) {
        int s = idx_at(ei, e, is64);
        int d = idx_at(ei, (long long)NE + e, is64);
        int p = atomicAdd(&g_pos[d], 1);
        g_src[p] = s;
    }
}

// ---------------- 3xTF32 tensor-core GEMM ------------------------------------
// g_xw[n,128] = A[n,128] @ W[128,128]
// 256 threads (8 warps), tile 128 rows x 128 cols, K in 16-wide panels.
// Each warp: 16 rows x 128 cols via m16n8k8 MMAs (16 n-tiles), 3 MMAs per
// (n-tile, k8) for the hi/lo split.
#define MB 128
__global__ __launch_bounds__(256) void k_gemm_tc(const float* __restrict__ Aext,
                                                 const float* __restrict__ W,
                                                 int a_is_h, int n) {
    const float* A = a_is_h ? g_h : Aext;
    __shared__ float2 As2[MB][17];     // [row][k]  (hi,lo) pairs, padded
    __shared__ float2 Ws2[16][130];    // [k][col]  (hi,lo) pairs, padded

    int tid = threadIdx.x;
    int row0 = blockIdx.x * MB;
    int lane = tid & 31, wid = tid >> 5;
    int wr = wid * 16;                 // warp row offset in tile
    int g = lane >> 2, tg = lane & 3;  // groupID, threadID-in-group

    float acc[16][4];
#pragma unroll
    for (int j = 0; j < 16; ++j)
#pragma unroll
        for (int q = 0; q < 4; ++q) acc[j][q] = 0.f;

    for (int k0 = 0; k0 < 128; k0 += 16) {
        // stage A panel: 128 rows x 16 k
#pragma unroll
        for (int it = 0; it < 2; ++it) {
            int idx = it * 256 + tid;          // 0..511
            int r = idx >> 2;
            int kq = (idx & 3) * 4;
            float4 v = make_float4(0.f, 0.f, 0.f, 0.f);
            if (row0 + r < n)
                v = *(const float4*)&A[(size_t)(row0 + r) * 128 + k0 + kq];
            As2[r][kq + 0] = split_tf32(v.x);
            As2[r][kq + 1] = split_tf32(v.y);
            As2[r][kq + 2] = split_tf32(v.z);
            As2[r][kq + 3] = split_tf32(v.w);
        }
        // stage W panel: 16 k x 128 cols
#pragma unroll
        for (int it = 0; it < 2; ++it) {
            int idx = it * 256 + tid;
            int kk = idx >> 5;                 // 0..15
            int cc = (idx & 31) * 4;
            float4 v = *(const float4*)&W[(size_t)(k0 + kk) * 128 + cc];
            Ws2[kk][cc + 0] = split_tf32(v.x);
            Ws2[kk][cc + 1] = split_tf32(v.y);
            Ws2[kk][cc + 2] = split_tf32(v.z);
            Ws2[kk][cc + 3] = split_tf32(v.w);
        }
        __syncthreads();
#pragma unroll
        for (int ks = 0; ks < 2; ++ks) {
            int k8 = ks * 8;
            float2 fa0 = As2[wr + g][k8 + tg];
            float2 fa1 = As2[wr + g + 8][k8 + tg];
            float2 fa2 = As2[wr + g][k8 + tg + 4];
            float2 fa3 = As2[wr + g + 8][k8 + tg + 4];
            unsigned ah0 = __float_as_uint(fa0.x), al0 = __float_as_uint(fa0.y);
            unsigned ah1 = __float_as_uint(fa1.x), al1 = __float_as_uint(fa1.y);
            unsigned ah2 = __float_as_uint(fa2.x), al2 = __float_as_uint(fa2.y);
            unsigned ah3 = __float_as_uint(fa3.x), al3 = __float_as_uint(fa3.y);
#pragma unroll
            for (int j = 0; j < 16; ++j) {
                float2 fb0 = Ws2[k8 + tg][j * 8 + g];
                float2 fb1 = Ws2[k8 + tg + 4][j * 8 + g];
                unsigned bh0 = __float_as_uint(fb0.x), bl0 = __float_as_uint(fb0.y);
                unsigned bh1 = __float_as_uint(fb1.x), bl1 = __float_as_uint(fb1.y);
                MMA_TF32(acc[j], ah0, ah1, ah2, ah3, bh0, bh1);
                MMA_TF32(acc[j], ah0, ah1, ah2, ah3, bl0, bl1);
                MMA_TF32(acc[j], al0, al1, al2, al3, bh0, bh1);
            }
        }
        __syncthreads();
    }
    // epilogue
    int r0 = row0 + wr + g;
#pragma unroll
    for (int j = 0; j < 16; ++j) {
        int c = j * 8 + 2 * tg;
        if (r0 < n)
            *(float2*)&g_xw[(size_t)r0 * 128 + c] = make_float2(acc[j][0], acc[j][1]);
        if (r0 + 8 < n)
            *(float2*)&g_xw[(size_t)(r0 + 8) * 128 + c] = make_float2(acc[j][2], acc[j][3]);
    }
}

// ---------------- aggregation: one warp per destination node -----------------
__global__ void k_agg(const float* __restrict__ bias, int dorelu) {
    int warp = (blockIdx.x * blockDim.x + threadIdx.x) >> 5;
    if (warp >= NN) return;
    int lane = threadIdx.x & 31;
    float di = g_dinv[warp];
    const float4* xw4 = (const float4*)g_xw;

    float4 v0 = xw4[(size_t)warp * 32 + lane];
    float4 acc = make_float4(v0.x * di, v0.y * di, v0.z * di, v0.w * di);

    int e0 = g_off[warp], e1 = g_off[warp + 1];
    for (int e = e0; e < e1; e += 32) {
        int cnt = min(32, e1 - e);
        int sidx = (lane < cnt) ? g_src[e + lane] : 0;
        float dv = (lane < cnt) ? g_dinv[sidx] : 0.f;
        for (int j = 0; j < cnt; ++j) {
            int s = __shfl_sync(0xffffffffu, sidx, j);
            float w = __shfl_sync(0xffffffffu, dv, j);
            float4 v = xw4[(size_t)s * 32 + lane];
            acc.x += v.x * w;
            acc.y += v.y * w;
            acc.z += v.z * w;
            acc.w += v.w * w;
        }
    }
    float4 bb = ((const float4*)bias)[lane];
    acc.x = acc.x * di + bb.x;
    acc.y = acc.y * di + bb.y;
    acc.z = acc.z * di + bb.z;
    acc.w = acc.w * di + bb.w;
    if (dorelu) {
        acc.x = fmaxf(acc.x, 0.f);
        acc.y = fmaxf(acc.y, 0.f);
        acc.z = fmaxf(acc.z, 0.f);
        acc.w = fmaxf(acc.w, 0.f);
    }
    ((float4*)g_h)[(size_t)warp * 32 + lane] = acc;
}

// ---------------- pooling ------------------------------------------------------
#define PNODES 256
__global__ void k_pool(const void* __restrict__ batch) {
    int t = threadIdx.x;
    int start = blockIdx.x * PNODES;
    int end = min(start + PNODES, NN);
    if (start >= NN) return;
    int is64 = g_is64;
    float acc = 0.f;
    int gprev = idx_at(batch, start, is64);
    for (int i = start; i < end; ++i) {
        int gq = idx_at(batch, i, is64);
        if (gq != gprev) {
            atomicAdd(&g_pool[gprev * DIM + t], acc);
            acc = 0.f;
            gprev = gq;
        }
        acc += g_h[(size_t)i * DIM + t];
    }
    atomicAdd(&g_pool[gprev * DIM + t], acc);
}

__global__ void k_final(const float* __restrict__ Wc, const float* __restrict__ bc,
                        float* __restrict__ out) {
    __shared__ float gs[DIM];
    int b = blockIdx.x, t = threadIdx.x;
    float c = fmaxf(g_cnt[b], 1.f);
    gs[t] = g_pool[b * DIM + t] / c;
    __syncthreads();
    if (t < NC) {
        float s = bc[t];
#pragma unroll 16
        for (int k = 0; k < DIM; ++k) s += gs[k] * Wc[k * NC + t];
        out[b * NC + t] = s;
    }
}

// ---------------- launch -------------------------------------------------------
extern "C" void kernel_launch(void* const* d_in, const int* in_sizes, int n_in,
                              void* d_out, int out_size) {
    const float* x     = (const float*)d_in[0];
    const void*  ei    = d_in[1];
    const void*  batch = d_in[2];
    const float* W1    = (const float*)d_in[3];
    const float* b1    = (const float*)d_in[4];
    const float* W2    = (const float*)d_in[5];
    const float* b2    = (const float*)d_in[6];
    const float* Wc    = (const float*)d_in[7];
    const float* bc    = (const float*)d_in[8];
    float*       out   = (float*)d_out;

    k_probe<<<1, 32>>>(ei);
    k_zero<<<256, 256>>>();
    k_hist<<<512, 256>>>(ei, batch);
    k_scan_local<<<NBLK, SCAN_B>>>();
    k_scan_blocks<<<1, 32>>>();
    k_scan_add<<<(NN + 255) / 256, 256>>>();
    k_csr<<<512, 256>>>(ei);

    int gemm_blocks = (NN + MB - 1) / MB;
    int agg_blocks = (NN * 32 + 255) / 256;

    // layer 1
    k_gemm_tc<<<gemm_blocks, 256>>>(x, W1, 0, NN);
    k_agg<<<agg_blocks, 256>>>(b1, 1);
    // layer 2
    k_gemm_tc<<<gemm_blocks, 256>>>(nullptr, W2, 1, NN);
    k_agg<<<agg_blocks, 256>>>(b2, 0);
    // pooling + classifier
    k_pool<<<(NN + PNODES - 1) / PNODES, DIM>>>(batch);
    k_final<<<NG, DIM>>>(Wc, bc, out);
}

// round 7
// speedup vs baseline: 1.1753x; 1.0206x over previous
#include <cuda_runtime.h>
#include <cuda_bf16.h>
#include <cstdint>

#define NN 100000
#define NE 1600000
#define NG 512
#define DIM 128
#define NC 10
#define SCAN_B 1024
#define NBLK ((NN + SCAN_B - 1) / SCAN_B)

// ---------------- scratch (device globals) ------------------------------------
__device__ int            g_is64;
__device__ int            g_deg[NN];
__device__ float          g_dinv[NN];
__device__ int            g_off[NN + 1];
__device__ int            g_pos[NN];
__device__ int            g_src[NE];
__device__ int            g_bsum[NBLK];
__device__ float          g_xw[(size_t)NN * DIM];
__device__ float          g_h[(size_t)NN * DIM];
__device__ float          g_pool[NG * DIM];
__device__ float          g_cnt[NG];
__device__ unsigned short g_wb[2][2][16384];  // [layer][hi/lo][n*128+k]  B=W^T bf16

__device__ __forceinline__ int idx_at(const void* p, long long i, int is64) {
    return is64 ? (int)((const long long*)p)[i] : ((const int*)p)[i];
}
__device__ __forceinline__ unsigned short bf16bits(float v) {
    __nv_bfloat16 h = __float2bfloat16(v);
    return *reinterpret_cast<unsigned short*>(&h);
}
__device__ __forceinline__ float bf16val(float v) {
    return __bfloat162float(__float2bfloat16(v));
}
__device__ __forceinline__ uint32_t smem_u32(const void* p) {
    uint32_t a;
    asm("{ .reg .u64 t; cvta.to.shared.u64 t, %1; cvt.u32.u64 %0, t; }" : "=r"(a) : "l"(p));
    return a;
}

#define LDSM4(r0, r1, r2, r3, addr)                                         \
    asm volatile("ldmatrix.sync.aligned.m8n8.x4.shared.b16 {%0,%1,%2,%3}, [%4];" \
                 : "=r"(r0), "=r"(r1), "=r"(r2), "=r"(r3) : "r"(addr))

#define MMA_BF16(d, a0, a1, a2, a3, b0, b1)                                  \
    asm volatile("mma.sync.aligned.m16n8k16.row.col.f32.bf16.bf16.f32 "      \
                 "{%0,%1,%2,%3},{%4,%5,%6,%7},{%8,%9},{%0,%1,%2,%3};"        \
                 : "+f"(d[0]), "+f"(d[1]), "+f"(d[2]), "+f"(d[3])            \
                 : "r"(a0), "r"(a1), "r"(a2), "r"(a3), "r"(b0), "r"(b1))

// ---------------- dtype probe -------------------------------------------------
__global__ void k_probe(const void* ei) {
    if (threadIdx.x == 0 && blockIdx.x == 0) {
        const int* w = (const int*)ei;
        int nz = 0;
        for (int i = 0; i < 128; ++i) nz += (w[2 * i + 1] != 0);
        g_is64 = (nz == 0) ? 1 : 0;
    }
}

// ---------------- setup -------------------------------------------------------
__global__ void k_zero() {
    int i = blockIdx.x * blockDim.x + threadIdx.x;
    int stride = gridDim.x * blockDim.x;
    for (int j = i; j < NN; j += stride) g_deg[j] = 0;
    for (int j = i; j < NG * DIM; j += stride) g_pool[j] = 0.f;
    for (int j = i; j < NG; j += stride) g_cnt[j] = 0.f;
}

// W[k][n] -> B[n][k] bf16 hi/lo for both layers
__global__ void k_wprep(const float* __restrict__ W1, const float* __restrict__ W2) {
    int i = blockIdx.x * blockDim.x + threadIdx.x;
    int stride = gridDim.x * blockDim.x;
    for (int e = i; e < 2 * 16384; e += stride) {
        int l = e >> 14;
        int idx = e & 16383;
        int nrow = idx >> 7, k = idx & 127;
        const float* W = l ? W2 : W1;
        float v = W[k * 128 + nrow];
        float hi = bf16val(v);
        g_wb[l][0][idx] = bf16bits(v);
        g_wb[l][1][idx] = bf16bits(v - hi);
    }
}

__global__ void k_hist(const void* __restrict__ ei, const void* __restrict__ batch) {
    int i = blockIdx.x * blockDim.x + threadIdx.x;
    int stride = gridDim.x * blockDim.x;
    int is64 = g_is64;
    for (int e = i; e < NE; e += stride) {
        int d = idx_at(ei, (long long)NE + e, is64);
        atomicAdd(&g_deg[d], 1);
    }
    for (int j = i; j < NN; j += stride)
        atomicAdd(&g_cnt[idx_at(batch, j, is64)], 1.f);
}

__global__ void k_scan_local() {
    __shared__ int s[SCAN_B];
    int t = threadIdx.x;
    int idx = blockIdx.x * SCAN_B + t;
    int v = (idx < NN) ? g_deg[idx] : 0;
    if (idx < NN) g_dinv[idx] = rsqrtf((float)(v + 1));
    s[t] = v;
    __syncthreads();
    for (int d = 1; d < SCAN_B; d <<= 1) {
        int x = (t >= d) ? s[t - d] : 0;
        __syncthreads();
        s[t] += x;
        __syncthreads();
    }
    if (idx < NN) g_off[idx] = s[t] - v;
    if (t == SCAN_B - 1) g_bsum[blockIdx.x] = s[t];
}

__global__ void k_scan_blocks() {
    if (threadIdx.x == 0 && blockIdx.x == 0) {
        int run = 0;
        for (int b = 0; b < NBLK; ++b) { int v = g_bsum[b]; g_bsum[b] = run; run += v; }
    }
}

__global__ void k_scan_add() {
    int idx = blockIdx.x * blockDim.x + threadIdx.x;
    if (idx < NN) {
        int o = g_off[idx] + g_bsum[idx / SCAN_B];
        g_off[idx] = o;
        g_pos[idx] = o;
    }
    if (idx == 0) g_off[NN] = NE;
}

__global__ void k_csr(const void* __restrict__ ei) {
    int i = blockIdx.x * blockDim.x + threadIdx.x;
    int stride = gridDim.x * blockDim.x;
    int is64 = g_is64;
    for (int e = i; e < NE; e += stride) {
        int s = idx_at(ei, e, is64);
        int d = idx_at(ei, (long long)NE + e, is64);
        int p = atomicAdd(&g_pos[d], 1);
        g_src[p] = s;
    }
}

// ---------------- bf16 3-split tensor GEMM (mma.m16n8k16 + ldmatrix) ---------
// g_xw[row0..row0+127, 0..127] = A @ W, W pre-split in g_wb[wsel]
// smem layout (bf16, row stride 136 elem = 272 B, conflict-free for ldmatrix):
#define AST 136
#define SM_AH 0
#define SM_AL 34816
#define SM_WH 69632
#define SM_WL 104448
#define GEMM_SMEM 139264

__global__ __launch_bounds__(256) void k_gemm_tc(const float* __restrict__ Aext,
                                                 int a_is_h, int wsel, int n) {
    extern __shared__ char smem[];
    uint32_t sb = smem_u32(smem);
    const float* A = a_is_h ? g_h : Aext;
    int tid = threadIdx.x, wid = tid >> 5, lane = tid & 31;
    int row0 = blockIdx.x * 128;

    // ---- stage A (fp32 -> bf16 hi/lo) ----
    unsigned short* ah = (unsigned short*)(smem + SM_AH);
    unsigned short* al = (unsigned short*)(smem + SM_AL);
    for (int idx = tid; idx < 4096; idx += 256) {
        int row = idx >> 5;
        int kq = (idx & 31) * 4;
        float4 v = make_float4(0.f, 0.f, 0.f, 0.f);
        if (row0 + row < n)
            v = *(const float4*)&A[(size_t)(row0 + row) * 128 + kq];
        ushort4 h4, l4;
        h4.x = bf16bits(v.x); l4.x = bf16bits(v.x - bf16val(v.x));
        h4.y = bf16bits(v.y); l4.y = bf16bits(v.y - bf16val(v.y));
        h4.z = bf16bits(v.z); l4.z = bf16bits(v.z - bf16val(v.z));
        h4.w = bf16bits(v.w); l4.w = bf16bits(v.w - bf16val(v.w));
        *(ushort4*)&ah[row * AST + kq] = h4;
        *(ushort4*)&al[row * AST + kq] = l4;
    }
    // ---- stage W (bf16, raw copy into padded layout) ----
    {
        unsigned short* wh = (unsigned short*)(smem + SM_WH);
        unsigned short* wl = (unsigned short*)(smem + SM_WL);
        for (int idx = tid; idx < 2048; idx += 256) {
            int nr = idx >> 4;
            int kq = (idx & 15) * 8;
            *(uint4*)&wh[nr * AST + kq] = *(const uint4*)&g_wb[wsel][0][nr * 128 + kq];
            *(uint4*)&wl[nr * AST + kq] = *(const uint4*)&g_wb[wsel][1][nr * 128 + kq];
        }
    }
    __syncthreads();

    // ---- mainloop ----
    float acc[16][4];
#pragma unroll
    for (int j = 0; j < 16; ++j)
#pragma unroll
        for (int q = 0; q < 4; ++q) acc[j][q] = 0.f;

    int wr = wid * 16;
    uint32_t a_off = (uint32_t)(((wr + (lane & 15)) * AST + ((lane >> 4) << 3)) * 2);
    uint32_t b_off = (uint32_t)((((lane & 7) + ((lane >> 4) << 3)) * AST +
                                 (((lane >> 3) & 1) << 3)) * 2);
    uint32_t ah_addr = sb + SM_AH + a_off;
    uint32_t al_addr = sb + SM_AL + a_off;
    uint32_t bh_base = sb + SM_WH + b_off;
    uint32_t bl_base = sb + SM_WL + b_off;

#pragma unroll
    for (int p = 0; p < 8; ++p) {
        uint32_t ka = p * 32;              // advance 16 bf16 along k
        uint32_t ah0, ah1, ah2, ah3, al0, al1, al2, al3;
        LDSM4(ah0, ah1, ah2, ah3, ah_addr + ka);
        LDSM4(al0, al1, al2, al3, al_addr + ka);
#pragma unroll
        for (int jj = 0; jj < 8; ++jj) {
            uint32_t bo = jj * (16 * AST * 2) + ka;
            uint32_t bh0, bh1, bh2, bh3, bl0, bl1, bl2, bl3;
            LDSM4(bh0, bh1, bh2, bh3, bh_base + bo);
            LDSM4(bl0, bl1, bl2, bl3, bl_base + bo);
            MMA_BF16(acc[2 * jj],     ah0, ah1, ah2, ah3, bh0, bh1);
            MMA_BF16(acc[2 * jj],     ah0, ah1, ah2, ah3, bl0, bl1);
            MMA_BF16(acc[2 * jj],     al0, al1, al2, al3, bh0, bh1);
            MMA_BF16(acc[2 * jj + 1], ah0, ah1, ah2, ah3, bh2, bh3);
            MMA_BF16(acc[2 * jj + 1], ah0, ah1, ah2, ah3, bl2, bl3);
            MMA_BF16(acc[2 * jj + 1], al0, al1, al2, al3, bh2, bh3);
        }
    }

    // ---- epilogue: direct float2 stores ----
    int r0 = row0 + wr + (lane >> 2);
    int cb = (lane & 3) * 2;
#pragma unroll
    for (int j = 0; j < 16; ++j) {
        int c = j * 8 + cb;
        if (r0 < n)
            *(float2*)&g_xw[(size_t)r0 * 128 + c] = make_float2(acc[j][0], acc[j][1]);
        if (r0 + 8 < n)
            *(float2*)&g_xw[(size_t)(r0 + 8) * 128 + c] = make_float2(acc[j][2], acc[j][3]);
    }
}

// ---------------- aggregation: one warp per destination node -----------------
__global__ void k_agg(const float* __restrict__ bias, int dorelu) {
    int warp = (blockIdx.x * blockDim.x + threadIdx.x) >> 5;
    if (warp >= NN) return;
    int lane = threadIdx.x & 31;
    float di = g_dinv[warp];
    const float4* xw4 = (const float4*)g_xw;

    float4 v0 = xw4[(size_t)warp * 32 + lane];
    float4 acc = make_float4(v0.x * di, v0.y * di, v0.z * di, v0.w * di);

    int e0 = g_off[warp], e1 = g_off[warp + 1];
    for (int e = e0; e < e1; e += 32) {
        int cnt = min(32, e1 - e);
        int sidx = (lane < cnt) ? g_src[e + lane] : 0;
        float dv = (lane < cnt) ? g_dinv[sidx] : 0.f;
        for (int j = 0; j < cnt; ++j) {
            int s = __shfl_sync(0xffffffffu, sidx, j);
            float w = __shfl_sync(0xffffffffu, dv, j);
            float4 v = xw4[(size_t)s * 32 + lane];
            acc.x += v.x * w;
            acc.y += v.y * w;
            acc.z += v.z * w;
            acc.w += v.w * w;
        }
    }
    float4 bb = ((const float4*)bias)[lane];
    acc.x = acc.x * di + bb.x;
    acc.y = acc.y * di + bb.y;
    acc.z = acc.z * di + bb.z;
    acc.w = acc.w * di + bb.w;
    if (dorelu) {
        acc.x = fmaxf(acc.x, 0.f);
        acc.y = fmaxf(acc.y, 0.f);
        acc.z = fmaxf(acc.z, 0.f);
        acc.w = fmaxf(acc.w, 0.f);
    }
    ((float4*)g_h)[(size_t)warp * 32 + lane] = acc;
}

// ---------------- pooling ------------------------------------------------------
#define PNODES 256
__global__ void k_pool(const void* __restrict__ batch) {
    int t = threadIdx.x;
    int start = blockIdx.x * PNODES;
    int end = min(start + PNODES, NN);
    if (start >= NN) return;
    int is64 = g_is64;
    float acc = 0.f;
    int gprev = idx_at(batch, start, is64);
    for (int i = start; i < end; ++i) {
        int gq = idx_at(batch, i, is64);
        if (gq != gprev) {
            atomicAdd(&g_pool[gprev * DIM + t], acc);
            acc = 0.f;
            gprev = gq;
        }
        acc += g_h[(size_t)i * DIM + t];
    }
    atomicAdd(&g_pool[gprev * DIM + t], acc);
}

__global__ void k_final(const float* __restrict__ Wc, const float* __restrict__ bc,
                        float* __restrict__ out) {
    __shared__ float gs[DIM];
    int b = blockIdx.x, t = threadIdx.x;
    float c = fmaxf(g_cnt[b], 1.f);
    gs[t] = g_pool[b * DIM + t] / c;
    __syncthreads();
    if (t < NC) {
        float s = bc[t];
#pragma unroll 16
        for (int k = 0; k < DIM; ++k) s += gs[k] * Wc[k * NC + t];
        out[b * NC + t] = s;
    }
}

// ---------------- launch -------------------------------------------------------
extern "C" void kernel_launch(void* const* d_in, const int* in_sizes, int n_in,
                              void* d_out, int out_size) {
    const float* x     = (const float*)d_in[0];
    const void*  ei    = d_in[1];
    const void*  batch = d_in[2];
    const float* W1    = (const float*)d_in[3];
    const float* b1    = (const float*)d_in[4];
    const float* W2    = (const float*)d_in[5];
    const float* b2    = (const float*)d_in[6];
    const float* Wc    = (const float*)d_in[7];
    const float* bc    = (const float*)d_in[8];
    float*       out   = (float*)d_out;

    cudaFuncSetAttribute(k_gemm_tc, cudaFuncAttributeMaxDynamicSharedMemorySize, GEMM_SMEM);

    int gemm_blocks = (NN + 127) / 128;
    int agg_blocks = (NN * 32 + 255) / 256;

    k_probe<<<1, 32>>>(ei);                                       // 0
    k_zero<<<256, 256>>>();                                       // 1
    k_wprep<<<64, 256>>>(W1, W2);                                 // 2
    k_gemm_tc<<<gemm_blocks, 256, GEMM_SMEM>>>(x, 0, 0, NN);      // 3 <- profiled
    k_hist<<<512, 256>>>(ei, batch);
    k_scan_local<<<NBLK, SCAN_B>>>();
    k_scan_blocks<<<1, 32>>>();
    k_scan_add<<<(NN + 255) / 256, 256>>>();
    k_csr<<<512, 256>>>(ei);
    k_agg<<<agg_blocks, 256>>>(b1, 1);
    k_gemm_tc<<<gemm_blocks, 256, GEMM_SMEM>>>(nullptr, 1, 1, NN);
    k_agg<<<agg_blocks, 256>>>(b2, 0);
    k_pool<<<(NN + PNODES - 1) / PNODES, DIM>>>(batch);
    k_final<<<NG, DIM>>>(Wc, bc, out);
}

// round 8
// speedup vs baseline: 1.3033x; 1.1089x over previous
#include <cuda_runtime.h>
#include <cuda_bf16.h>
#include <cstdint>

#define NN 100000
#define NE 1600000
#define NG 512
#define DIM 128
#define NC 10
#define SCAN_B 1024
#define NBLK ((NN + SCAN_B - 1) / SCAN_B)

// ---------------- scratch (device globals) ------------------------------------
__device__ int            g_is64;
__device__ int            g_deg[NN];
__device__ float          g_dinv[NN];
__device__ int            g_off[NN + 1];
__device__ int            g_pos[NN];
__device__ int            g_src[NE];
__device__ int            g_bsum[NBLK];
__device__ float          g_xw[(size_t)NN * DIM];
__device__ float          g_h[(size_t)NN * DIM];
__device__ float          g_pool[NG * DIM];
__device__ float          g_cnt[NG];
__device__ unsigned short g_wb[2][2][16384];  // [layer][hi/lo][n*128+k]  B=W^T bf16

__device__ __forceinline__ int idx_at(const void* p, long long i, int is64) {
    return is64 ? (int)((const long long*)p)[i] : ((const int*)p)[i];
}
__device__ __forceinline__ unsigned short bf16bits(float v) {
    __nv_bfloat16 h = __float2bfloat16(v);
    return *reinterpret_cast<unsigned short*>(&h);
}
__device__ __forceinline__ float bf16val(float v) {
    return __bfloat162float(__float2bfloat16(v));
}
__device__ __forceinline__ uint32_t smem_u32(const void* p) {
    uint32_t a;
    asm("{ .reg .u64 t; cvta.to.shared.u64 t, %1; cvt.u32.u64 %0, t; }" : "=r"(a) : "l"(p));
    return a;
}

#define LDSM4(r0, r1, r2, r3, addr)                                         \
    asm volatile("ldmatrix.sync.aligned.m8n8.x4.shared.b16 {%0,%1,%2,%3}, [%4];" \
                 : "=r"(r0), "=r"(r1), "=r"(r2), "=r"(r3) : "r"(addr))

#define MMA_BF16(d, a0, a1, a2, a3, b0, b1)                                  \
    asm volatile("mma.sync.aligned.m16n8k16.row.col.f32.bf16.bf16.f32 "      \
                 "{%0,%1,%2,%3},{%4,%5,%6,%7},{%8,%9},{%0,%1,%2,%3};"        \
                 : "+f"(d[0]), "+f"(d[1]), "+f"(d[2]), "+f"(d[3])            \
                 : "r"(a0), "r"(a1), "r"(a2), "r"(a3), "r"(b0), "r"(b1))

// ---------------- dtype probe -------------------------------------------------
__global__ void k_probe(const void* ei) {
    if (threadIdx.x == 0 && blockIdx.x == 0) {
        const int* w = (const int*)ei;
        int nz = 0;
        for (int i = 0; i < 128; ++i) nz += (w[2 * i + 1] != 0);
        g_is64 = (nz == 0) ? 1 : 0;
    }
}

// ---------------- setup -------------------------------------------------------
__global__ void k_zero() {
    int i = blockIdx.x * blockDim.x + threadIdx.x;
    int stride = gridDim.x * blockDim.x;
    for (int j = i; j < NN; j += stride) g_deg[j] = 0;
    for (int j = i; j < NG * DIM; j += stride) g_pool[j] = 0.f;
    for (int j = i; j < NG; j += stride) g_cnt[j] = 0.f;
}

// W[k][n] -> B[n][k] bf16 hi/lo for both layers
__global__ void k_wprep(const float* __restrict__ W1, const float* __restrict__ W2) {
    int i = blockIdx.x * blockDim.x + threadIdx.x;
    int stride = gridDim.x * blockDim.x;
    for (int e = i; e < 2 * 16384; e += stride) {
        int l = e >> 14;
        int idx = e & 16383;
        int nrow = idx >> 7, k = idx & 127;
        const float* W = l ? W2 : W1;
        float v = W[k * 128 + nrow];
        float hi = bf16val(v);
        g_wb[l][0][idx] = bf16bits(v);
        g_wb[l][1][idx] = bf16bits(v - hi);
    }
}

__global__ void k_hist(const void* __restrict__ ei, const void* __restrict__ batch) {
    int i = blockIdx.x * blockDim.x + threadIdx.x;
    int stride = gridDim.x * blockDim.x;
    int is64 = g_is64;
    for (int e = i; e < NE; e += stride) {
        int d = idx_at(ei, (long long)NE + e, is64);
        atomicAdd(&g_deg[d], 1);
    }
    for (int j = i; j < NN; j += stride)
        atomicAdd(&g_cnt[idx_at(batch, j, is64)], 1.f);
}

__global__ void k_scan_local() {
    __shared__ int s[SCAN_B];
    int t = threadIdx.x;
    int idx = blockIdx.x * SCAN_B + t;
    int v = (idx < NN) ? g_deg[idx] : 0;
    if (idx < NN) g_dinv[idx] = rsqrtf((float)(v + 1));
    s[t] = v;
    __syncthreads();
    for (int d = 1; d < SCAN_B; d <<= 1) {
        int x = (t >= d) ? s[t - d] : 0;
        __syncthreads();
        s[t] += x;
        __syncthreads();
    }
    if (idx < NN) g_off[idx] = s[t] - v;
    if (t == SCAN_B - 1) g_bsum[blockIdx.x] = s[t];
}

__global__ void k_scan_blocks() {
    if (threadIdx.x == 0 && blockIdx.x == 0) {
        int run = 0;
        for (int b = 0; b < NBLK; ++b) { int v = g_bsum[b]; g_bsum[b] = run; run += v; }
    }
}

__global__ void k_scan_add() {
    int idx = blockIdx.x * blockDim.x + threadIdx.x;
    if (idx < NN) {
        int o = g_off[idx] + g_bsum[idx / SCAN_B];
        g_off[idx] = o;
        g_pos[idx] = o;
    }
    if (idx == 0) g_off[NN] = NE;
}

__global__ void k_csr(const void* __restrict__ ei) {
    int i = blockIdx.x * blockDim.x + threadIdx.x;
    int stride = gridDim.x * blockDim.x;
    int is64 = g_is64;
    for (int e = i; e < NE; e += stride) {
        int s = idx_at(ei, e, is64);
        int d = idx_at(ei, (long long)NE + e, is64);
        int p = atomicAdd(&g_pos[d], 1);
        g_src[p] = s;
    }
}

// ---------------- bf16 3-split tensor GEMM (mma.m16n8k16 + ldmatrix) ---------
// 512 threads, 16 warps in 8x2 grid: warp = 16 rows x 64 cols.
#define AST 136
#define SM_AH 0
#define SM_AL 34816
#define SM_WH 69632
#define SM_WL 104448
#define GEMM_SMEM 139264

__global__ __launch_bounds__(512) void k_gemm_tc(const float* __restrict__ Aext,
                                                 int a_is_h, int wsel, int n) {
    extern __shared__ char smem[];
    uint32_t sb = smem_u32(smem);
    const float* A = a_is_h ? g_h : Aext;
    int tid = threadIdx.x, wid = tid >> 5, lane = tid & 31;
    int row0 = blockIdx.x * 128;

    // ---- stage A (fp32 -> bf16 hi/lo) ----
    unsigned short* ah = (unsigned short*)(smem + SM_AH);
    unsigned short* al = (unsigned short*)(smem + SM_AL);
    for (int idx = tid; idx < 4096; idx += 512) {
        int row = idx >> 5;
        int kq = (idx & 31) * 4;
        float4 v = make_float4(0.f, 0.f, 0.f, 0.f);
        if (row0 + row < n)
            v = *(const float4*)&A[(size_t)(row0 + row) * 128 + kq];
        ushort4 h4, l4;
        h4.x = bf16bits(v.x); l4.x = bf16bits(v.x - bf16val(v.x));
        h4.y = bf16bits(v.y); l4.y = bf16bits(v.y - bf16val(v.y));
        h4.z = bf16bits(v.z); l4.z = bf16bits(v.z - bf16val(v.z));
        h4.w = bf16bits(v.w); l4.w = bf16bits(v.w - bf16val(v.w));
        *(ushort4*)&ah[row * AST + kq] = h4;
        *(ushort4*)&al[row * AST + kq] = l4;
    }
    // ---- stage W (bf16, raw copy into padded layout) ----
    {
        unsigned short* wh = (unsigned short*)(smem + SM_WH);
        unsigned short* wl = (unsigned short*)(smem + SM_WL);
        for (int idx = tid; idx < 2048; idx += 512) {
            int nr = idx >> 4;
            int kq = (idx & 15) * 8;
            *(uint4*)&wh[nr * AST + kq] = *(const uint4*)&g_wb[wsel][0][nr * 128 + kq];
            *(uint4*)&wl[nr * AST + kq] = *(const uint4*)&g_wb[wsel][1][nr * 128 + kq];
        }
    }
    __syncthreads();

    // ---- mainloop: warp (r,c): rows r*16.., cols c*64.. ----
    float acc[8][4];
#pragma unroll
    for (int j = 0; j < 8; ++j)
#pragma unroll
        for (int q = 0; q < 4; ++q) acc[j][q] = 0.f;

    int wr = (wid >> 1) * 16;
    int wc = (wid & 1) * 64;
    uint32_t a_off = (uint32_t)(((wr + (lane & 15)) * AST + ((lane >> 4) << 3)) * 2);
    uint32_t b_off = (uint32_t)(((wc + (lane & 7) + ((lane >> 4) << 3)) * AST +
                                 (((lane >> 3) & 1) << 3)) * 2);
    uint32_t ah_addr = sb + SM_AH + a_off;
    uint32_t al_addr = sb + SM_AL + a_off;
    uint32_t bh_base = sb + SM_WH + b_off;
    uint32_t bl_base = sb + SM_WL + b_off;

#pragma unroll
    for (int p = 0; p < 8; ++p) {
        uint32_t ka = p * 32;
        uint32_t ah0, ah1, ah2, ah3, al0, al1, al2, al3;
        LDSM4(ah0, ah1, ah2, ah3, ah_addr + ka);
        LDSM4(al0, al1, al2, al3, al_addr + ka);
#pragma unroll
        for (int jj = 0; jj < 4; ++jj) {
            uint32_t bo = jj * (16 * AST * 2) + ka;
            uint32_t bh0, bh1, bh2, bh3, bl0, bl1, bl2, bl3;
            LDSM4(bh0, bh1, bh2, bh3, bh_base + bo);
            LDSM4(bl0, bl1, bl2, bl3, bl_base + bo);
            // interleave even/odd accumulators to break RAW chains
            MMA_BF16(acc[2 * jj],     ah0, ah1, ah2, ah3, bh0, bh1);
            MMA_BF16(acc[2 * jj + 1], ah0, ah1, ah2, ah3, bh2, bh3);
            MMA_BF16(acc[2 * jj],     ah0, ah1, ah2, ah3, bl0, bl1);
            MMA_BF16(acc[2 * jj + 1], ah0, ah1, ah2, ah3, bl2, bl3);
            MMA_BF16(acc[2 * jj],     al0, al1, al2, al3, bh0, bh1);
            MMA_BF16(acc[2 * jj + 1], al0, al1, al2, al3, bh2, bh3);
        }
    }

    // ---- epilogue: direct float2 stores ----
    int r0 = row0 + wr + (lane >> 2);
    int cb = wc + (lane & 3) * 2;
#pragma unroll
    for (int j = 0; j < 8; ++j) {
        int c = cb + j * 8;
        if (r0 < n)
            *(float2*)&g_xw[(size_t)r0 * 128 + c] = make_float2(acc[j][0], acc[j][1]);
        if (r0 + 8 < n)
            *(float2*)&g_xw[(size_t)(r0 + 8) * 128 + c] = make_float2(acc[j][2], acc[j][3]);
    }
}

// ---------------- aggregation: one warp per destination node -----------------
__global__ void k_agg(const float* __restrict__ bias, int dorelu) {
    int warp = (blockIdx.x * blockDim.x + threadIdx.x) >> 5;
    if (warp >= NN) return;
    int lane = threadIdx.x & 31;
    float di = g_dinv[warp];
    const float4* xw4 = (const float4*)g_xw;

    float4 v0 = xw4[(size_t)warp * 32 + lane];
    float4 acc = make_float4(v0.x * di, v0.y * di, v0.z * di, v0.w * di);

    int e0 = g_off[warp], e1 = g_off[warp + 1];
    for (int e = e0; e < e1; e += 32) {
        int cnt = min(32, e1 - e);
        int sidx = (lane < cnt) ? g_src[e + lane] : 0;
        float dv = (lane < cnt) ? g_dinv[sidx] : 0.f;
        for (int j = 0; j < cnt; ++j) {
            int s = __shfl_sync(0xffffffffu, sidx, j);
            float w = __shfl_sync(0xffffffffu, dv, j);
            float4 v = xw4[(size_t)s * 32 + lane];
            acc.x += v.x * w;
            acc.y += v.y * w;
            acc.z += v.z * w;
            acc.w += v.w * w;
        }
    }
    float4 bb = ((const float4*)bias)[lane];
    acc.x = acc.x * di + bb.x;
    acc.y = acc.y * di + bb.y;
    acc.z = acc.z * di + bb.z;
    acc.w = acc.w * di + bb.w;
    if (dorelu) {
        acc.x = fmaxf(acc.x, 0.f);
        acc.y = fmaxf(acc.y, 0.f);
        acc.z = fmaxf(acc.z, 0.f);
        acc.w = fmaxf(acc.w, 0.f);
    }
    ((float4*)g_h)[(size_t)warp * 32 + lane] = acc;
}

// ---------------- pooling ------------------------------------------------------
#define PNODES 256
__global__ void k_pool(const void* __restrict__ batch) {
    int t = threadIdx.x;
    int start = blockIdx.x * PNODES;
    int end = min(start + PNODES, NN);
    if (start >= NN) return;
    int is64 = g_is64;
    float acc = 0.f;
    int gprev = idx_at(batch, start, is64);
    for (int i = start; i < end; ++i) {
        int gq = idx_at(batch, i, is64);
        if (gq != gprev) {
            atomicAdd(&g_pool[gprev * DIM + t], acc);
            acc = 0.f;
            gprev = gq;
        }
        acc += g_h[(size_t)i * DIM + t];
    }
    atomicAdd(&g_pool[gprev * DIM + t], acc);
}

__global__ void k_final(const float* __restrict__ Wc, const float* __restrict__ bc,
                        float* __restrict__ out) {
    __shared__ float gs[DIM];
    int b = blockIdx.x, t = threadIdx.x;
    float c = fmaxf(g_cnt[b], 1.f);
    gs[t] = g_pool[b * DIM + t] / c;
    __syncthreads();
    if (t < NC) {
        float s = bc[t];
#pragma unroll 16
        for (int k = 0; k < DIM; ++k) s += gs[k] * Wc[k * NC + t];
        out[b * NC + t] = s;
    }
}

// ---------------- launch -------------------------------------------------------
extern "C" void kernel_launch(void* const* d_in, const int* in_sizes, int n_in,
                              void* d_out, int out_size) {
    const float* x     = (const float*)d_in[0];
    const void*  ei    = d_in[1];
    const void*  batch = d_in[2];
    const float* W1    = (const float*)d_in[3];
    const float* b1    = (const float*)d_in[4];
    const float* W2    = (const float*)d_in[5];
    const float* b2    = (const float*)d_in[6];
    const float* Wc    = (const float*)d_in[7];
    const float* bc    = (const float*)d_in[8];
    float*       out   = (float*)d_out;

    cudaFuncSetAttribute(k_gemm_tc, cudaFuncAttributeMaxDynamicSharedMemorySize, GEMM_SMEM);

    int gemm_blocks = (NN + 127) / 128;
    int agg_blocks = (NN * 32 + 255) / 256;

    k_probe<<<1, 32>>>(ei);                                       // 0
    k_zero<<<256, 256>>>();                                       // 1
    k_wprep<<<64, 256>>>(W1, W2);                                 // 2
    k_gemm_tc<<<gemm_blocks, 512, GEMM_SMEM>>>(x, 0, 0, NN);      // 3 <- profiled
    k_hist<<<512, 256>>>(ei, batch);
    k_scan_local<<<NBLK, SCAN_B>>>();
    k_scan_blocks<<<1, 32>>>();
    k_scan_add<<<(NN + 255) / 256, 256>>>();
    k_csr<<<512, 256>>>(ei);
    k_agg<<<agg_blocks, 256>>>(b1, 1);
    k_gemm_tc<<<gemm_blocks, 512, GEMM_SMEM>>>(nullptr, 1, 1, NN);
    k_agg<<<agg_blocks, 256>>>(b2, 0);
    k_pool<<<(NN + PNODES - 1) / PNODES, DIM>>>(batch);
    k_final<<<NG, DIM>>>(Wc, bc, out);
}

// round 9
// speedup vs baseline: 1.5148x; 1.1623x over previous
#include <cuda_runtime.h>
#include <cuda_bf16.h>
#include <cuda_fp16.h>
#include <cstdint>

#define NN 100000
#define NE 1600000
#define NG 512
#define DIM 128
#define NC 10
#define SCAN_B 1024
#define NBLK ((NN + SCAN_B - 1) / SCAN_B)

// ---------------- scratch (device globals) ------------------------------------
__device__ int            g_is64;
__device__ int            g_deg[NN];
__device__ float          g_dinv[NN];
__device__ int            g_off[NN + 1];
__device__ int            g_pos[NN];
__device__ int            g_src[NE];
__device__ int            g_bsum[NBLK];
__device__ __half2        g_xw16[(size_t)NN * 64];   // GEMM output, fp16 (gathered)
__device__ float          g_h[(size_t)NN * DIM];     // agg output, fp32
__device__ float          g_pool[NG * DIM];
__device__ float          g_cnt[NG];
__device__ unsigned short g_wb[2][2][16384];  // [layer][hi/lo][n*128+k]  B=W^T bf16

__device__ __forceinline__ int idx_at(const void* p, long long i, int is64) {
    return is64 ? (int)((const long long*)p)[i] : ((const int*)p)[i];
}
__device__ __forceinline__ unsigned short bf16bits(float v) {
    __nv_bfloat16 h = __float2bfloat16(v);
    return *reinterpret_cast<unsigned short*>(&h);
}
__device__ __forceinline__ float bf16val(float v) {
    return __bfloat162float(__float2bfloat16(v));
}
__device__ __forceinline__ uint32_t smem_u32(const void* p) {
    uint32_t a;
    asm("{ .reg .u64 t; cvta.to.shared.u64 t, %1; cvt.u32.u64 %0, t; }" : "=r"(a) : "l"(p));
    return a;
}

#define LDSM4(r0, r1, r2, r3, addr)                                         \
    asm volatile("ldmatrix.sync.aligned.m8n8.x4.shared.b16 {%0,%1,%2,%3}, [%4];" \
                 : "=r"(r0), "=r"(r1), "=r"(r2), "=r"(r3) : "r"(addr))

#define MMA_BF16(d, a0, a1, a2, a3, b0, b1)                                  \
    asm volatile("mma.sync.aligned.m16n8k16.row.col.f32.bf16.bf16.f32 "      \
                 "{%0,%1,%2,%3},{%4,%5,%6,%7},{%8,%9},{%0,%1,%2,%3};"        \
                 : "+f"(d[0]), "+f"(d[1]), "+f"(d[2]), "+f"(d[3])            \
                 : "r"(a0), "r"(a1), "r"(a2), "r"(a3), "r"(b0), "r"(b1))

// ---------------- dtype probe -------------------------------------------------
__global__ void k_probe(const void* ei) {
    if (threadIdx.x == 0 && blockIdx.x == 0) {
        const int* w = (const int*)ei;
        int nz = 0;
        for (int i = 0; i < 128; ++i) nz += (w[2 * i + 1] != 0);
        g_is64 = (nz == 0) ? 1 : 0;
    }
}

// ---------------- setup -------------------------------------------------------
__global__ void k_zero() {
    int i = blockIdx.x * blockDim.x + threadIdx.x;
    int stride = gridDim.x * blockDim.x;
    for (int j = i; j < NN; j += stride) g_deg[j] = 0;
    for (int j = i; j < NG * DIM; j += stride) g_pool[j] = 0.f;
    for (int j = i; j < NG; j += stride) g_cnt[j] = 0.f;
}

// W[k][n] -> B[n][k] bf16 hi/lo for both layers
__global__ void k_wprep(const float* __restrict__ W1, const float* __restrict__ W2) {
    int i = blockIdx.x * blockDim.x + threadIdx.x;
    int stride = gridDim.x * blockDim.x;
    for (int e = i; e < 2 * 16384; e += stride) {
        int l = e >> 14;
        int idx = e & 16383;
        int nrow = idx >> 7, k = idx & 127;
        const float* W = l ? W2 : W1;
        float v = W[k * 128 + nrow];
        float hi = bf16val(v);
        g_wb[l][0][idx] = bf16bits(v);
        g_wb[l][1][idx] = bf16bits(v - hi);
    }
}

__global__ void k_hist(const void* __restrict__ ei, const void* __restrict__ batch) {
    int i = blockIdx.x * blockDim.x + threadIdx.x;
    int stride = gridDim.x * blockDim.x;
    int is64 = g_is64;
    for (int e = i; e < NE; e += stride) {
        int d = idx_at(ei, (long long)NE + e, is64);
        atomicAdd(&g_deg[d], 1);
    }
    for (int j = i; j < NN; j += stride)
        atomicAdd(&g_cnt[idx_at(batch, j, is64)], 1.f);
}

__global__ void k_scan_local() {
    __shared__ int s[SCAN_B];
    int t = threadIdx.x;
    int idx = blockIdx.x * SCAN_B + t;
    int v = (idx < NN) ? g_deg[idx] : 0;
    if (idx < NN) g_dinv[idx] = rsqrtf((float)(v + 1));
    s[t] = v;
    __syncthreads();
    for (int d = 1; d < SCAN_B; d <<= 1) {
        int x = (t >= d) ? s[t - d] : 0;
        __syncthreads();
        s[t] += x;
        __syncthreads();
    }
    if (idx < NN) g_off[idx] = s[t] - v;
    if (t == SCAN_B - 1) g_bsum[blockIdx.x] = s[t];
}

__global__ void k_scan_blocks() {
    if (threadIdx.x == 0 && blockIdx.x == 0) {
        int run = 0;
        for (int b = 0; b < NBLK; ++b) { int v = g_bsum[b]; g_bsum[b] = run; run += v; }
    }
}

__global__ void k_scan_add() {
    int idx = blockIdx.x * blockDim.x + threadIdx.x;
    if (idx < NN) {
        int o = g_off[idx] + g_bsum[idx / SCAN_B];
        g_off[idx] = o;
        g_pos[idx] = o;
    }
    if (idx == 0) g_off[NN] = NE;
}

__global__ void k_csr(const void* __restrict__ ei) {
    int i = blockIdx.x * blockDim.x + threadIdx.x;
    int stride = gridDim.x * blockDim.x;
    int is64 = g_is64;
    for (int e = i; e < NE; e += stride) {
        int s = idx_at(ei, e, is64);
        int d = idx_at(ei, (long long)NE + e, is64);
        int p = atomicAdd(&g_pos[d], 1);
        g_src[p] = s;
    }
}

// ---------------- bf16 3-split tensor GEMM -> fp16 output --------------------
// 64-row tiles, 512 threads (16 warps in 4x4 grid: warp = 16 rows x 32 cols).
// smem ~102KB -> 2 CTAs/SM.
#define AST 136
#define SM_AH 0
#define SM_AL 17408
#define SM_WH 34816
#define SM_WL 69632
#define GEMM_SMEM 104448

__global__ __launch_bounds__(512, 2) void k_gemm_tc(const float* __restrict__ Aext,
                                                    int a_is_h, int wsel, int n) {
    extern __shared__ char smem[];
    uint32_t sb = smem_u32(smem);
    const float* A = a_is_h ? g_h : Aext;
    int tid = threadIdx.x, wid = tid >> 5, lane = tid & 31;
    int row0 = blockIdx.x * 64;

    // ---- stage A (fp32 -> bf16 hi/lo): 64 rows x 128 k ----
    unsigned short* ah = (unsigned short*)(smem + SM_AH);
    unsigned short* al = (unsigned short*)(smem + SM_AL);
    for (int idx = tid; idx < 2048; idx += 512) {
        int row = idx >> 5;
        int kq = (idx & 31) * 4;
        float4 v = make_float4(0.f, 0.f, 0.f, 0.f);
        if (row0 + row < n)
            v = *(const float4*)&A[(size_t)(row0 + row) * 128 + kq];
        ushort4 h4, l4;
        h4.x = bf16bits(v.x); l4.x = bf16bits(v.x - bf16val(v.x));
        h4.y = bf16bits(v.y); l4.y = bf16bits(v.y - bf16val(v.y));
        h4.z = bf16bits(v.z); l4.z = bf16bits(v.z - bf16val(v.z));
        h4.w = bf16bits(v.w); l4.w = bf16bits(v.w - bf16val(v.w));
        *(ushort4*)&ah[row * AST + kq] = h4;
        *(ushort4*)&al[row * AST + kq] = l4;
    }
    // ---- stage W (raw copy): 128 n x 128 k ----
    {
        unsigned short* wh = (unsigned short*)(smem + SM_WH);
        unsigned short* wl = (unsigned short*)(smem + SM_WL);
        for (int idx = tid; idx < 2048; idx += 512) {
            int nr = idx >> 4;
            int kq = (idx & 15) * 8;
            *(uint4*)&wh[nr * AST + kq] = *(const uint4*)&g_wb[wsel][0][nr * 128 + kq];
            *(uint4*)&wl[nr * AST + kq] = *(const uint4*)&g_wb[wsel][1][nr * 128 + kq];
        }
    }
    __syncthreads();

    // ---- mainloop: warp (r,c): rows wr.., cols wc.. (16x32) ----
    float acc[4][4];
#pragma unroll
    for (int j = 0; j < 4; ++j)
#pragma unroll
        for (int q = 0; q < 4; ++q) acc[j][q] = 0.f;

    int wr = (wid >> 2) * 16;
    int wc = (wid & 3) * 32;
    uint32_t a_off = (uint32_t)(((wr + (lane & 15)) * AST + ((lane >> 4) << 3)) * 2);
    uint32_t b_off = (uint32_t)(((wc + (lane & 7) + ((lane >> 4) << 3)) * AST +
                                 (((lane >> 3) & 1) << 3)) * 2);
    uint32_t ah_addr = sb + SM_AH + a_off;
    uint32_t al_addr = sb + SM_AL + a_off;
    uint32_t bh_base = sb + SM_WH + b_off;
    uint32_t bl_base = sb + SM_WL + b_off;

#pragma unroll
    for (int p = 0; p < 8; ++p) {
        uint32_t ka = p * 32;
        uint32_t ah0, ah1, ah2, ah3, al0, al1, al2, al3;
        LDSM4(ah0, ah1, ah2, ah3, ah_addr + ka);
        LDSM4(al0, al1, al2, al3, al_addr + ka);
#pragma unroll
        for (int jj = 0; jj < 2; ++jj) {
            uint32_t bo = jj * (16 * AST * 2) + ka;
            uint32_t bh0, bh1, bh2, bh3, bl0, bl1, bl2, bl3;
            LDSM4(bh0, bh1, bh2, bh3, bh_base + bo);
            LDSM4(bl0, bl1, bl2, bl3, bl_base + bo);
            MMA_BF16(acc[2 * jj],     ah0, ah1, ah2, ah3, bh0, bh1);
            MMA_BF16(acc[2 * jj + 1], ah0, ah1, ah2, ah3, bh2, bh3);
            MMA_BF16(acc[2 * jj],     ah0, ah1, ah2, ah3, bl0, bl1);
            MMA_BF16(acc[2 * jj + 1], ah0, ah1, ah2, ah3, bl2, bl3);
            MMA_BF16(acc[2 * jj],     al0, al1, al2, al3, bh0, bh1);
            MMA_BF16(acc[2 * jj + 1], al0, al1, al2, al3, bh2, bh3);
        }
    }

    // ---- epilogue: fp16 stores ----
    int r0 = row0 + wr + (lane >> 2);
    int cb = wc + (lane & 3) * 2;
#pragma unroll
    for (int j = 0; j < 4; ++j) {
        int c = cb + j * 8;
        if (r0 < n)
            g_xw16[(size_t)r0 * 64 + (c >> 1)] = __floats2half2_rn(acc[j][0], acc[j][1]);
        if (r0 + 8 < n)
            g_xw16[(size_t)(r0 + 8) * 64 + (c >> 1)] = __floats2half2_rn(acc[j][2], acc[j][3]);
    }
}

// ---------------- aggregation: one warp per destination node -----------------
// fp16 gather, fp32 accumulate
__global__ void k_agg(const float* __restrict__ bias, int dorelu) {
    int warp = (blockIdx.x * blockDim.x + threadIdx.x) >> 5;
    if (warp >= NN) return;
    int lane = threadIdx.x & 31;
    float di = g_dinv[warp];
    const uint2* xw2 = (const uint2*)g_xw16;   // 32 uint2 per row (4 halves each)

    uint2 raw = xw2[(size_t)warp * 32 + lane];
    float2 f0 = __half22float2(*(__half2*)&raw.x);
    float2 f1 = __half22float2(*(__half2*)&raw.y);
    float4 acc = make_float4(f0.x * di, f0.y * di, f1.x * di, f1.y * di);

    int e0 = g_off[warp], e1 = g_off[warp + 1];
    for (int e = e0; e < e1; e += 32) {
        int cnt = min(32, e1 - e);
        int sidx = (lane < cnt) ? g_src[e + lane] : 0;
        float dv = (lane < cnt) ? g_dinv[sidx] : 0.f;
        for (int j = 0; j < cnt; ++j) {
            int s = __shfl_sync(0xffffffffu, sidx, j);
            float w = __shfl_sync(0xffffffffu, dv, j);
            uint2 r = xw2[(size_t)s * 32 + lane];
            float2 v0 = __half22float2(*(__half2*)&r.x);
            float2 v1 = __half22float2(*(__half2*)&r.y);
            acc.x += v0.x * w;
            acc.y += v0.y * w;
            acc.z += v1.x * w;
            acc.w += v1.y * w;
        }
    }
    float4 bb = ((const float4*)bias)[lane];
    acc.x = acc.x * di + bb.x;
    acc.y = acc.y * di + bb.y;
    acc.z = acc.z * di + bb.z;
    acc.w = acc.w * di + bb.w;
    if (dorelu) {
        acc.x = fmaxf(acc.x, 0.f);
        acc.y = fmaxf(acc.y, 0.f);
        acc.z = fmaxf(acc.z, 0.f);
        acc.w = fmaxf(acc.w, 0.f);
    }
    ((float4*)g_h)[(size_t)warp * 32 + lane] = acc;
}

// ---------------- pooling ------------------------------------------------------
#define PNODES 256
__global__ void k_pool(const void* __restrict__ batch) {
    int t = threadIdx.x;
    int start = blockIdx.x * PNODES;
    int end = min(start + PNODES, NN);
    if (start >= NN) return;
    int is64 = g_is64;
    float acc = 0.f;
    int gprev = idx_at(batch, start, is64);
    for (int i = start; i < end; ++i) {
        int gq = idx_at(batch, i, is64);
        if (gq != gprev) {
            atomicAdd(&g_pool[gprev * DIM + t], acc);
            acc = 0.f;
            gprev = gq;
        }
        acc += g_h[(size_t)i * DIM + t];
    }
    atomicAdd(&g_pool[gprev * DIM + t], acc);
}

__global__ void k_final(const float* __restrict__ Wc, const float* __restrict__ bc,
                        float* __restrict__ out) {
    __shared__ float gs[DIM];
    int b = blockIdx.x, t = threadIdx.x;
    float c = fmaxf(g_cnt[b], 1.f);
    gs[t] = g_pool[b * DIM + t] / c;
    __syncthreads();
    if (t < NC) {
        float s = bc[t];
#pragma unroll 16
        for (int k = 0; k < DIM; ++k) s += gs[k] * Wc[k * NC + t];
        out[b * NC + t] = s;
    }
}

// ---------------- launch -------------------------------------------------------
extern "C" void kernel_launch(void* const* d_in, const int* in_sizes, int n_in,
                              void* d_out, int out_size) {
    const float* x     = (const float*)d_in[0];
    const void*  ei    = d_in[1];
    const void*  batch = d_in[2];
    const float* W1    = (const float*)d_in[3];
    const float* b1    = (const float*)d_in[4];
    const float* W2    = (const float*)d_in[5];
    const float* b2    = (const float*)d_in[6];
    const float* Wc    = (const float*)d_in[7];
    const float* bc    = (const float*)d_in[8];
    float*       out   = (float*)d_out;

    cudaFuncSetAttribute(k_gemm_tc, cudaFuncAttributeMaxDynamicSharedMemorySize, GEMM_SMEM);

    int gemm_blocks = (NN + 63) / 64;
    int agg_blocks = (NN * 32 + 255) / 256;

    k_probe<<<1, 32>>>(ei);                                       // 0
    k_zero<<<256, 256>>>();                                       // 1
    k_wprep<<<64, 256>>>(W1, W2);                                 // 2
    k_gemm_tc<<<gemm_blocks, 512, GEMM_SMEM>>>(x, 0, 0, NN);      // 3 <- profiled
    k_hist<<<512, 256>>>(ei, batch);
    k_scan_local<<<NBLK, SCAN_B>>>();
    k_scan_blocks<<<1, 32>>>();
    k_scan_add<<<(NN + 255) / 256, 256>>>();
    k_csr<<<512, 256>>>(ei);
    k_agg<<<agg_blocks, 256>>>(b1, 1);
    k_gemm_tc<<<gemm_blocks, 512, GEMM_SMEM>>>(nullptr, 1, 1, NN);
    k_agg<<<agg_blocks, 256>>>(b2, 0);
    k_pool<<<(NN + PNODES - 1) / PNODES, DIM>>>(batch);
    k_final<<<NG, DIM>>>(Wc, bc, out);
}

// round 10
// speedup vs baseline: 1.5508x; 1.0237x over previous
#include <cuda_runtime.h>
#include <cuda_bf16.h>
#include <cuda_fp16.h>
#include <cstdint>

#define NN 100000
#define NE 1600000
#define NG 512
#define DIM 128
#define NC 10
#define SCAN_B 1024
#define NBLK ((NN + SCAN_B - 1) / SCAN_B)

// ---------------- scratch (device globals) ------------------------------------
__device__ int            g_is64;
__device__ int            g_deg[NN];
__device__ float          g_dinv[NN];
__device__ int            g_off[NN + 1];
__device__ int            g_pos[NN];
__device__ int            g_src[NE];
__device__ int            g_bsum[NBLK];
__device__ __half2        g_xw16[(size_t)NN * 64];   // GEMM output, fp16 (gathered)
__device__ float          g_h[(size_t)NN * DIM];     // agg output, fp32
__device__ float          g_pool[NG * DIM];
__device__ float          g_cnt[NG];
__device__ unsigned short g_wb[2][2][16384];  // [layer][hi/lo][n*128+k]  B=W^T bf16

__device__ __forceinline__ int idx_at(const void* p, long long i, int is64) {
    return is64 ? (int)((const long long*)p)[i] : ((const int*)p)[i];
}
__device__ __forceinline__ unsigned short bf16bits(float v) {
    __nv_bfloat16 h = __float2bfloat16(v);
    return *reinterpret_cast<unsigned short*>(&h);
}
__device__ __forceinline__ float bf16val(float v) {
    return __bfloat162float(__float2bfloat16(v));
}
__device__ __forceinline__ uint32_t smem_u32(const void* p) {
    uint32_t a;
    asm("{ .reg .u64 t; cvta.to.shared.u64 t, %1; cvt.u32.u64 %0, t; }" : "=r"(a) : "l"(p));
    return a;
}

#define LDSM4(r0, r1, r2, r3, addr)                                         \
    asm volatile("ldmatrix.sync.aligned.m8n8.x4.shared.b16 {%0,%1,%2,%3}, [%4];" \
                 : "=r"(r0), "=r"(r1), "=r"(r2), "=r"(r3) : "r"(addr))

#define MMA_BF16(d, a0, a1, a2, a3, b0, b1)                                  \
    asm volatile("mma.sync.aligned.m16n8k16.row.col.f32.bf16.bf16.f32 "      \
                 "{%0,%1,%2,%3},{%4,%5,%6,%7},{%8,%9},{%0,%1,%2,%3};"        \
                 : "+f"(d[0]), "+f"(d[1]), "+f"(d[2]), "+f"(d[3])            \
                 : "r"(a0), "r"(a1), "r"(a2), "r"(a3), "r"(b0), "r"(b1))

// ---------------- setup (zero + dtype probe merged) ----------------------------
__global__ void k_zero(const void* ei) {
    if (blockIdx.x == 0 && threadIdx.x == 0) {
        const int* w = (const int*)ei;
        int nz = 0;
        for (int i = 0; i < 128; ++i) nz += (w[2 * i + 1] != 0);
        g_is64 = (nz == 0) ? 1 : 0;
    }
    int i = blockIdx.x * blockDim.x + threadIdx.x;
    int stride = gridDim.x * blockDim.x;
    for (int j = i; j < NN; j += stride) g_deg[j] = 0;
    for (int j = i; j < NG * DIM; j += stride) g_pool[j] = 0.f;
    for (int j = i; j < NG; j += stride) g_cnt[j] = 0.f;
}

// W[k][n] -> B[n][k] bf16 hi/lo for both layers
__global__ void k_wprep(const float* __restrict__ W1, const float* __restrict__ W2) {
    int i = blockIdx.x * blockDim.x + threadIdx.x;
    int stride = gridDim.x * blockDim.x;
    for (int e = i; e < 2 * 16384; e += stride) {
        int l = e >> 14;
        int idx = e & 16383;
        int nrow = idx >> 7, k = idx & 127;
        const float* W = l ? W2 : W1;
        float v = W[k * 128 + nrow];
        float hi = bf16val(v);
        g_wb[l][0][idx] = bf16bits(v);
        g_wb[l][1][idx] = bf16bits(v - hi);
    }
}

__global__ void k_hist(const void* __restrict__ ei, const void* __restrict__ batch) {
    int i = blockIdx.x * blockDim.x + threadIdx.x;
    int stride = gridDim.x * blockDim.x;
    int is64 = g_is64;
    for (int e = i; e < NE; e += stride) {
        int d = idx_at(ei, (long long)NE + e, is64);
        atomicAdd(&g_deg[d], 1);
    }
    for (int j = i; j < NN; j += stride)
        atomicAdd(&g_cnt[idx_at(batch, j, is64)], 1.f);
}

__global__ void k_scan_local() {
    __shared__ int s[SCAN_B];
    int t = threadIdx.x;
    int idx = blockIdx.x * SCAN_B + t;
    int v = (idx < NN) ? g_deg[idx] : 0;
    if (idx < NN) g_dinv[idx] = rsqrtf((float)(v + 1));
    s[t] = v;
    __syncthreads();
    for (int d = 1; d < SCAN_B; d <<= 1) {
        int x = (t >= d) ? s[t - d] : 0;
        __syncthreads();
        s[t] += x;
        __syncthreads();
    }
    if (idx < NN) g_off[idx] = s[t] - v;
    if (t == SCAN_B - 1) g_bsum[blockIdx.x] = s[t];
}

// parallel exclusive scan of the 98 block sums (single block)
__global__ void k_scan_blocks() {
    __shared__ int s[128];
    int t = threadIdx.x;
    int v = (t < NBLK) ? g_bsum[t] : 0;
    s[t] = v;
    __syncthreads();
    for (int d = 1; d < 128; d <<= 1) {
        int x = (t >= d) ? s[t - d] : 0;
        __syncthreads();
        s[t] += x;
        __syncthreads();
    }
    if (t < NBLK) g_bsum[t] = s[t] - v;   // exclusive
}

__global__ void k_scan_add() {
    int idx = blockIdx.x * blockDim.x + threadIdx.x;
    if (idx < NN) {
        int o = g_off[idx] + g_bsum[idx / SCAN_B];
        g_off[idx] = o;
        g_pos[idx] = o;
    }
    if (idx == 0) g_off[NN] = NE;
}

__global__ void k_csr(const void* __restrict__ ei) {
    int i = blockIdx.x * blockDim.x + threadIdx.x;
    int stride = gridDim.x * blockDim.x;
    int is64 = g_is64;
    for (int e = i; e < NE; e += stride) {
        int s = idx_at(ei, e, is64);
        int d = idx_at(ei, (long long)NE + e, is64);
        int p = atomicAdd(&g_pos[d], 1);
        g_src[p] = s;
    }
}

// ---------------- bf16 3-split tensor GEMM -> fp16 output --------------------
// 64-row tiles, 512 threads, 2 column passes of 64 cols (W restaged per pass).
// smem ~68KB -> 3 CTAs/SM. Warp grid 4x4: warp = 16 rows x 16 cols per pass.
#define AST 136
#define SM_AH 0
#define SM_AL 17408
#define SM_WH 34816
#define SM_WL 52224
#define GEMM_SMEM 69632

__global__ __launch_bounds__(512, 3) void k_gemm_tc(const float* __restrict__ Aext,
                                                    int a_is_h, int wsel, int n) {
    extern __shared__ char smem[];
    uint32_t sb = smem_u32(smem);
    const float* A = a_is_h ? g_h : Aext;
    int tid = threadIdx.x, wid = tid >> 5, lane = tid & 31;
    int row0 = blockIdx.x * 64;

    // ---- stage A (fp32 -> bf16 hi/lo): 64 rows x 128 k ----
    unsigned short* ah = (unsigned short*)(smem + SM_AH);
    unsigned short* al = (unsigned short*)(smem + SM_AL);
    for (int idx = tid; idx < 2048; idx += 512) {
        int row = idx >> 5;
        int kq = (idx & 31) * 4;
        float4 v = make_float4(0.f, 0.f, 0.f, 0.f);
        if (row0 + row < n)
            v = *(const float4*)&A[(size_t)(row0 + row) * 128 + kq];
        ushort4 h4, l4;
        h4.x = bf16bits(v.x); l4.x = bf16bits(v.x - bf16val(v.x));
        h4.y = bf16bits(v.y); l4.y = bf16bits(v.y - bf16val(v.y));
        h4.z = bf16bits(v.z); l4.z = bf16bits(v.z - bf16val(v.z));
        h4.w = bf16bits(v.w); l4.w = bf16bits(v.w - bf16val(v.w));
        *(ushort4*)&ah[row * AST + kq] = h4;
        *(ushort4*)&al[row * AST + kq] = l4;
    }

    int wr = (wid >> 2) * 16;
    int wc = (wid & 3) * 16;
    uint32_t a_off = (uint32_t)(((wr + (lane & 15)) * AST + ((lane >> 4) << 3)) * 2);
    uint32_t b_off = (uint32_t)(((wc + (lane & 7) + ((lane >> 4) << 3)) * AST +
                                 (((lane >> 3) & 1) << 3)) * 2);
    uint32_t ah_addr = sb + SM_AH + a_off;
    uint32_t al_addr = sb + SM_AL + a_off;
    uint32_t bh_addr = sb + SM_WH + b_off;
    uint32_t bl_addr = sb + SM_WL + b_off;

    unsigned short* wh = (unsigned short*)(smem + SM_WH);
    unsigned short* wl = (unsigned short*)(smem + SM_WL);

#pragma unroll
    for (int cpass = 0; cpass < 2; ++cpass) {
        // ---- stage W half: 64 n-rows x 128 k ----
        for (int idx = tid; idx < 1024; idx += 512) {
            int nr = idx >> 4;
            int kq = (idx & 15) * 8;
            int src = (cpass * 64 + nr) * 128 + kq;
            *(uint4*)&wh[nr * AST + kq] = *(const uint4*)&g_wb[wsel][0][src];
            *(uint4*)&wl[nr * AST + kq] = *(const uint4*)&g_wb[wsel][1][src];
        }
        __syncthreads();

        float acc[2][4];
#pragma unroll
        for (int j = 0; j < 2; ++j)
#pragma unroll
            for (int q = 0; q < 4; ++q) acc[j][q] = 0.f;

#pragma unroll
        for (int p = 0; p < 8; ++p) {
            uint32_t ka = p * 32;
            uint32_t ah0, ah1, ah2, ah3, al0, al1, al2, al3;
            uint32_t bh0, bh1, bh2, bh3, bl0, bl1, bl2, bl3;
            LDSM4(ah0, ah1, ah2, ah3, ah_addr + ka);
            LDSM4(al0, al1, al2, al3, al_addr + ka);
            LDSM4(bh0, bh1, bh2, bh3, bh_addr + ka);
            LDSM4(bl0, bl1, bl2, bl3, bl_addr + ka);
            MMA_BF16(acc[0], ah0, ah1, ah2, ah3, bh0, bh1);
            MMA_BF16(acc[1], ah0, ah1, ah2, ah3, bh2, bh3);
            MMA_BF16(acc[0], ah0, ah1, ah2, ah3, bl0, bl1);
            MMA_BF16(acc[1], ah0, ah1, ah2, ah3, bl2, bl3);
            MMA_BF16(acc[0], al0, al1, al2, al3, bh0, bh1);
            MMA_BF16(acc[1], al0, al1, al2, al3, bh2, bh3);
        }

        // ---- epilogue: fp16 stores for this 64-col half ----
        int r0 = row0 + wr + (lane >> 2);
        int cb = cpass * 64 + wc + (lane & 3) * 2;
#pragma unroll
        for (int j = 0; j < 2; ++j) {
            int c = cb + j * 8;
            if (r0 < n)
                g_xw16[(size_t)r0 * 64 + (c >> 1)] = __floats2half2_rn(acc[j][0], acc[j][1]);
            if (r0 + 8 < n)
                g_xw16[(size_t)(r0 + 8) * 64 + (c >> 1)] = __floats2half2_rn(acc[j][2], acc[j][3]);
        }
        __syncthreads();   // all reads of W done before restage
    }
}

// ---------------- aggregation: one warp per destination node -----------------
// fp16 gather, fp32 accumulate
__global__ void k_agg(const float* __restrict__ bias, int dorelu) {
    int warp = (blockIdx.x * blockDim.x + threadIdx.x) >> 5;
    if (warp >= NN) return;
    int lane = threadIdx.x & 31;
    float di = g_dinv[warp];
    const uint2* xw2 = (const uint2*)g_xw16;

    uint2 raw = xw2[(size_t)warp * 32 + lane];
    float2 f0 = __half22float2(*(__half2*)&raw.x);
    float2 f1 = __half22float2(*(__half2*)&raw.y);
    float4 acc = make_float4(f0.x * di, f0.y * di, f1.x * di, f1.y * di);

    int e0 = g_off[warp], e1 = g_off[warp + 1];
    for (int e = e0; e < e1; e += 32) {
        int cnt = min(32, e1 - e);
        int sidx = (lane < cnt) ? g_src[e + lane] : 0;
        float dv = (lane < cnt) ? g_dinv[sidx] : 0.f;
#pragma unroll 4
        for (int j = 0; j < cnt; ++j) {
            int s = __shfl_sync(0xffffffffu, sidx, j);
            float w = __shfl_sync(0xffffffffu, dv, j);
            uint2 r = xw2[(size_t)s * 32 + lane];
            float2 v0 = __half22float2(*(__half2*)&r.x);
            float2 v1 = __half22float2(*(__half2*)&r.y);
            acc.x += v0.x * w;
            acc.y += v0.y * w;
            acc.z += v1.x * w;
            acc.w += v1.y * w;
        }
    }
    float4 bb = ((const float4*)bias)[lane];
    acc.x = acc.x * di + bb.x;
    acc.y = acc.y * di + bb.y;
    acc.z = acc.z * di + bb.z;
    acc.w = acc.w * di + bb.w;
    if (dorelu) {
        acc.x = fmaxf(acc.x, 0.f);
        acc.y = fmaxf(acc.y, 0.f);
        acc.z = fmaxf(acc.z, 0.f);
        acc.w = fmaxf(acc.w, 0.f);
    }
    ((float4*)g_h)[(size_t)warp * 32 + lane] = acc;
}

// ---------------- pooling ------------------------------------------------------
#define PNODES 256
__global__ void k_pool(const void* __restrict__ batch) {
    int t = threadIdx.x;
    int start = blockIdx.x * PNODES;
    int end = min(start + PNODES, NN);
    if (start >= NN) return;
    int is64 = g_is64;
    float acc = 0.f;
    int gprev = idx_at(batch, start, is64);
    for (int i = start; i < end; ++i) {
        int gq = idx_at(batch, i, is64);
        if (gq != gprev) {
            atomicAdd(&g_pool[gprev * DIM + t], acc);
            acc = 0.f;
            gprev = gq;
        }
        acc += g_h[(size_t)i * DIM + t];
    }
    atomicAdd(&g_pool[gprev * DIM + t], acc);
}

__global__ void k_final(const float* __restrict__ Wc, const float* __restrict__ bc,
                        float* __restrict__ out) {
    __shared__ float gs[DIM];
    int b = blockIdx.x, t = threadIdx.x;
    float c = fmaxf(g_cnt[b], 1.f);
    gs[t] = g_pool[b * DIM + t] / c;
    __syncthreads();
    if (t < NC) {
        float s = bc[t];
#pragma unroll 16
        for (int k = 0; k < DIM; ++k) s += gs[k] * Wc[k * NC + t];
        out[b * NC + t] = s;
    }
}

// ---------------- launch -------------------------------------------------------
extern "C" void kernel_launch(void* const* d_in, const int* in_sizes, int n_in,
                              void* d_out, int out_size) {
    const float* x     = (const float*)d_in[0];
    const void*  ei    = d_in[1];
    const void*  batch = d_in[2];
    const float* W1    = (const float*)d_in[3];
    const float* b1    = (const float*)d_in[4];
    const float* W2    = (const float*)d_in[5];
    const float* b2    = (const float*)d_in[6];
    const float* Wc    = (const float*)d_in[7];
    const float* bc    = (const float*)d_in[8];
    float*       out   = (float*)d_out;

    cudaFuncSetAttribute(k_gemm_tc, cudaFuncAttributeMaxDynamicSharedMemorySize, GEMM_SMEM);

    int gemm_blocks = (NN + 63) / 64;
    int agg_blocks = (NN * 32 + 255) / 256;

    k_zero<<<256, 256>>>(ei);                                     // 0 (incl. probe)
    k_wprep<<<64, 256>>>(W1, W2);                                 // 1
    k_hist<<<512, 256>>>(ei, batch);                              // 2
    k_gemm_tc<<<gemm_blocks, 512, GEMM_SMEM>>>(x, 0, 0, NN);      // 3 <- profiled
    k_scan_local<<<NBLK, SCAN_B>>>();                             // 4
    k_scan_blocks<<<1, 128>>>();                                  // 5
    k_scan_add<<<(NN + 255) / 256, 256>>>();                      // 6
    k_csr<<<512, 256>>>(ei);                                      // 7
    k_agg<<<agg_blocks, 256>>>(b1, 1);                            // 8
    k_gemm_tc<<<gemm_blocks, 512, GEMM_SMEM>>>(nullptr, 1, 1, NN);// 9
    k_agg<<<agg_blocks, 256>>>(b2, 0);                            // 10
    k_pool<<<(NN + PNODES - 1) / PNODES, DIM>>>(batch);           // 11
    k_final<<<NG, DIM>>>(Wc, bc, out);                            // 12
}

// round 12
// speedup vs baseline: 1.8438x; 1.1890x over previous
#include <cuda_runtime.h>
#include <cuda_bf16.h>
#include <cuda_fp16.h>
#include <cstdint>

#define NN 100000
#define NE 1600000
#define NG 512
#define DIM 128
#define NC 10
#define SCAN_B 1024
#define NBLK ((NN + SCAN_B - 1) / SCAN_B)

// ---------------- scratch (device globals) ------------------------------------
__device__ int            g_is64;
__device__ int            g_deg[NN];
__device__ float          g_dinv[NN];
__device__ int            g_off[NN + 1];
__device__ int            g_pos[NN];
__device__ int            g_src[NE];
__device__ int            g_bsum[NBLK];
__device__ __half2        g_xw16[(size_t)NN * 64];   // GEMM output, fp16 (gathered)
__device__ __half2        g_h16[(size_t)NN * 64];    // agg output, fp16
__device__ float          g_pool[NG * DIM];
__device__ float          g_cnt[NG];
__device__ unsigned short g_wb[2][2][16384];  // [layer][hi/lo][n*128+k]  B=W^T fp16

__device__ __forceinline__ int idx_at(const void* p, long long i, int is64) {
    return is64 ? (int)((const long long*)p)[i] : ((const int*)p)[i];
}
__device__ __forceinline__ unsigned short f16bits(float v) {
    __half h = __float2half_rn(v);
    return *reinterpret_cast<unsigned short*>(&h);
}
__device__ __forceinline__ float f16val(float v) {
    return __half2float(__float2half_rn(v));
}
__device__ __forceinline__ uint32_t h2u(__half2 h) {
    return *reinterpret_cast<uint32_t*>(&h);
}
__device__ __forceinline__ uint32_t smem_u32(const void* p) {
    uint32_t a;
    asm("{ .reg .u64 t; cvta.to.shared.u64 t, %1; cvt.u32.u64 %0, t; }" : "=r"(a) : "l"(p));
    return a;
}

#define LDSM4(r0, r1, r2, r3, addr)                                         \
    asm volatile("ldmatrix.sync.aligned.m8n8.x4.shared.b16 {%0,%1,%2,%3}, [%4];" \
                 : "=r"(r0), "=r"(r1), "=r"(r2), "=r"(r3) : "r"(addr))

#define MMA_F16(d, a0, a1, a2, a3, b0, b1)                                   \
    asm volatile("mma.sync.aligned.m16n8k16.row.col.f32.f16.f16.f32 "        \
                 "{%0,%1,%2,%3},{%4,%5,%6,%7},{%8,%9},{%0,%1,%2,%3};"        \
                 : "+f"(d[0]), "+f"(d[1]), "+f"(d[2]), "+f"(d[3])            \
                 : "r"(a0), "r"(a1), "r"(a2), "r"(a3), "r"(b0), "r"(b1))

// ---------------- setup (zero + dtype probe merged) ----------------------------
__global__ void k_zero(const void* ei) {
    if (blockIdx.x == 0 && threadIdx.x == 0) {
        const int* w = (const int*)ei;
        int nz = 0;
        for (int i = 0; i < 128; ++i) nz += (w[2 * i + 1] != 0);
        g_is64 = (nz == 0) ? 1 : 0;
    }
    int i = blockIdx.x * blockDim.x + threadIdx.x;
    int stride = gridDim.x * blockDim.x;
    for (int j = i; j < NN; j += stride) g_deg[j] = 0;
    for (int j = i; j < NG * DIM; j += stride) g_pool[j] = 0.f;
    for (int j = i; j < NG; j += stride) g_cnt[j] = 0.f;
}

// W[k][n] -> B[n][k] fp16 hi/lo for both layers
__global__ void k_wprep(const float* __restrict__ W1, const float* __restrict__ W2) {
    int i = blockIdx.x * blockDim.x + threadIdx.x;
    int stride = gridDim.x * blockDim.x;
    for (int e = i; e < 2 * 16384; e += stride) {
        int l = e >> 14;
        int idx = e & 16383;
        int nrow = idx >> 7, k = idx & 127;
        const float* W = l ? W2 : W1;
        float v = W[k * 128 + nrow];
        float hi = f16val(v);
        g_wb[l][0][idx] = f16bits(v);
        g_wb[l][1][idx] = f16bits(v - hi);
    }
}

__global__ void k_hist(const void* __restrict__ ei, const void* __restrict__ batch) {
    int i = blockIdx.x * blockDim.x + threadIdx.x;
    int stride = gridDim.x * blockDim.x;
    int is64 = g_is64;
    for (int e = i; e < NE; e += stride) {
        int d = idx_at(ei, (long long)NE + e, is64);
        atomicAdd(&g_deg[d], 1);
    }
    for (int j = i; j < NN; j += stride)
        atomicAdd(&g_cnt[idx_at(batch, j, is64)], 1.f);
}

__global__ void k_scan_local() {
    __shared__ int s[SCAN_B];
    int t = threadIdx.x;
    int idx = blockIdx.x * SCAN_B + t;
    int v = (idx < NN) ? g_deg[idx] : 0;
    if (idx < NN) g_dinv[idx] = rsqrtf((float)(v + 1));
    s[t] = v;
    __syncthreads();
    for (int d = 1; d < SCAN_B; d <<= 1) {
        int x = (t >= d) ? s[t - d] : 0;
        __syncthreads();
        s[t] += x;
        __syncthreads();
    }
    if (idx < NN) g_off[idx] = s[t] - v;
    if (t == SCAN_B - 1) g_bsum[blockIdx.x] = s[t];
}

// parallel exclusive scan of the block sums (single block)
__global__ void k_scan_blocks() {
    __shared__ int s[128];
    int t = threadIdx.x;
    int v = (t < NBLK) ? g_bsum[t] : 0;
    s[t] = v;
    __syncthreads();
    for (int d = 1; d < 128; d <<= 1) {
        int x = (t >= d) ? s[t - d] : 0;
        __syncthreads();
        s[t] += x;
        __syncthreads();
    }
    if (t < NBLK) g_bsum[t] = s[t] - v;   // exclusive
}

__global__ void k_scan_add() {
    int idx = blockIdx.x * blockDim.x + threadIdx.x;
    if (idx < NN) {
        int o = g_off[idx] + g_bsum[idx / SCAN_B];
        g_off[idx] = o;
        g_pos[idx] = o;
    }
    if (idx == 0) g_off[NN] = NE;
}

__global__ void k_csr(const void* __restrict__ ei) {
    int i = blockIdx.x * blockDim.x + threadIdx.x;
    int stride = gridDim.x * blockDim.x;
    int is64 = g_is64;
    for (int e = i; e < NE; e += stride) {
        int s = idx_at(ei, e, is64);
        int d = idx_at(ei, (long long)NE + e, is64);
        int p = atomicAdd(&g_pos[d], 1);
        g_src[p] = s;
    }
}

// ---------------- fp16 2-term tensor GEMM -> fp16 output ---------------------
// D = A(fp16) * (Wh + Wl).  64-row tiles, 512 threads, 2 column passes.
// smem 52KB -> 4 CTAs/SM target. Warp grid 4x4: warp = 16 rows x 16 cols/pass.
#define AST 136
#define SM_A  0
#define SM_WH 17408
#define SM_WL 34816
#define GEMM_SMEM 52224

__global__ __launch_bounds__(512, 4) void k_gemm_tc(const float* __restrict__ Aext,
                                                    int a_is_h16, int wsel, int n) {
    extern __shared__ char smem[];
    uint32_t sb = smem_u32(smem);
    int tid = threadIdx.x, wid = tid >> 5, lane = tid & 31;
    int row0 = blockIdx.x * 64;

    // ---- stage A (fp16): 64 rows x 128 k ----
    unsigned short* as = (unsigned short*)(smem + SM_A);
    if (a_is_h16) {
        // raw copy from g_h16 (already fp16)
        for (int idx = tid; idx < 1024; idx += 512) {
            int row = idx >> 4;
            int ch = idx & 15;                     // uint4 chunk (8 halves)
            uint4 v = make_uint4(0, 0, 0, 0);
            if (row0 + row < n)
                v = ((const uint4*)g_h16)[(size_t)(row0 + row) * 16 + ch];
            *(uint4*)&as[row * AST + ch * 8] = v;
        }
    } else {
        for (int idx = tid; idx < 1024; idx += 512) {
            int row = idx >> 4;
            int ch = idx & 15;
            float4 v0 = make_float4(0.f, 0.f, 0.f, 0.f), v1 = v0;
            if (row0 + row < n) {
                const float* src = &Aext[(size_t)(row0 + row) * 128 + ch * 8];
                v0 = *(const float4*)src;
                v1 = *(const float4*)(src + 4);
            }
            uint4 o;
            o.x = h2u(__floats2half2_rn(v0.x, v0.y));
            o.y = h2u(__floats2half2_rn(v0.z, v0.w));
            o.z = h2u(__floats2half2_rn(v1.x, v1.y));
            o.w = h2u(__floats2half2_rn(v1.z, v1.w));
            *(uint4*)&as[row * AST + ch * 8] = o;
        }
    }

    int wr = (wid >> 2) * 16;
    int wc = (wid & 3) * 16;
    uint32_t a_off = (uint32_t)(((wr + (lane & 15)) * AST + ((lane >> 4) << 3)) * 2);
    uint32_t b_off = (uint32_t)(((wc + (lane & 7) + ((lane >> 4) << 3)) * AST +
                                 (((lane >> 3) & 1) << 3)) * 2);
    uint32_t a_addr  = sb + SM_A + a_off;
    uint32_t bh_addr = sb + SM_WH + b_off;
    uint32_t bl_addr = sb + SM_WL + b_off;

    unsigned short* wh = (unsigned short*)(smem + SM_WH);
    unsigned short* wl = (unsigned short*)(smem + SM_WL);

#pragma unroll
    for (int cpass = 0; cpass < 2; ++cpass) {
        // ---- stage W half: 64 n-rows x 128 k ----
        for (int idx = tid; idx < 1024; idx += 512) {
            int nr = idx >> 4;
            int kq = (idx & 15) * 8;
            int src = (cpass * 64 + nr) * 128 + kq;
            *(uint4*)&wh[nr * AST + kq] = *(const uint4*)&g_wb[wsel][0][src];
            *(uint4*)&wl[nr * AST + kq] = *(const uint4*)&g_wb[wsel][1][src];
        }
        __syncthreads();

        float acc[2][4];
#pragma unroll
        for (int j = 0; j < 2; ++j)
#pragma unroll
            for (int q = 0; q < 4; ++q) acc[j][q] = 0.f;

#pragma unroll
        for (int p = 0; p < 8; ++p) {
            uint32_t ka = p * 32;
            uint32_t a0, a1, a2, a3;
            uint32_t bh0, bh1, bh2, bh3, bl0, bl1, bl2, bl3;
            LDSM4(a0, a1, a2, a3, a_addr + ka);
            LDSM4(bh0, bh1, bh2, bh3, bh_addr + ka);
            LDSM4(bl0, bl1, bl2, bl3, bl_addr + ka);
            MMA_F16(acc[0], a0, a1, a2, a3, bh0, bh1);
            MMA_F16(acc[1], a0, a1, a2, a3, bh2, bh3);
            MMA_F16(acc[0], a0, a1, a2, a3, bl0, bl1);
            MMA_F16(acc[1], a0, a1, a2, a3, bl2, bl3);
        }

        // ---- epilogue: fp16 stores for this 64-col half ----
        int r0 = row0 + wr + (lane >> 2);
        int cb = cpass * 64 + wc + (lane & 3) * 2;
#pragma unroll
        for (int j = 0; j < 2; ++j) {
            int c = cb + j * 8;
            if (r0 < n)
                g_xw16[(size_t)r0 * 64 + (c >> 1)] = __floats2half2_rn(acc[j][0], acc[j][1]);
            if (r0 + 8 < n)
                g_xw16[(size_t)(r0 + 8) * 64 + (c >> 1)] = __floats2half2_rn(acc[j][2], acc[j][3]);
        }
        __syncthreads();   // all reads of W done before restage
    }
}

// ---------------- aggregation: one warp per destination node -----------------
// fp16 gather, fp32 accumulate, fp16 output
__global__ void k_agg(const float* __restrict__ bias, int dorelu) {
    int warp = (blockIdx.x * blockDim.x + threadIdx.x) >> 5;
    if (warp >= NN) return;
    int lane = threadIdx.x & 31;
    float di = g_dinv[warp];
    const uint2* xw2 = (const uint2*)g_xw16;

    uint2 raw = xw2[(size_t)warp * 32 + lane];
    float2 f0 = __half22float2(*(__half2*)&raw.x);
    float2 f1 = __half22float2(*(__half2*)&raw.y);
    float4 acc = make_float4(f0.x * di, f0.y * di, f1.x * di, f1.y * di);

    int e0 = g_off[warp], e1 = g_off[warp + 1];
    for (int e = e0; e < e1; e += 32) {
        int cnt = min(32, e1 - e);
        int sidx = (lane < cnt) ? g_src[e + lane] : 0;
        float dv = (lane < cnt) ? g_dinv[sidx] : 0.f;
#pragma unroll 4
        for (int j = 0; j < cnt; ++j) {
            int s = __shfl_sync(0xffffffffu, sidx, j);
            float w = __shfl_sync(0xffffffffu, dv, j);
            uint2 r = xw2[(size_t)s * 32 + lane];
            float2 v0 = __half22float2(*(__half2*)&r.x);
            float2 v1 = __half22float2(*(__half2*)&r.y);
            acc.x += v0.x * w;
            acc.y += v0.y * w;
            acc.z += v1.x * w;
            acc.w += v1.y * w;
        }
    }
    float4 bb = ((const float4*)bias)[lane];
    acc.x = acc.x * di + bb.x;
    acc.y = acc.y * di + bb.y;
    acc.z = acc.z * di + bb.z;
    acc.w = acc.w * di + bb.w;
    if (dorelu) {
        acc.x = fmaxf(acc.x, 0.f);
        acc.y = fmaxf(acc.y, 0.f);
        acc.z = fmaxf(acc.z, 0.f);
        acc.w = fmaxf(acc.w, 0.f);
    }
    uint2 o;
    o.x = h2u(__floats2half2_rn(acc.x, acc.y));
    o.y = h2u(__floats2half2_rn(acc.z, acc.w));
    ((uint2*)g_h16)[(size_t)warp * 32 + lane] = o;
}

// ---------------- pooling ------------------------------------------------------
#define PNODES 256
__global__ void k_pool(const void* __restrict__ batch) {
    int t = threadIdx.x;
    int start = blockIdx.x * PNODES;
    int end = min(start + PNODES, NN);
    if (start >= NN) return;
    int is64 = g_is64;
    const __half* h = (const __half*)g_h16;
    float acc = 0.f;
    int gprev = idx_at(batch, start, is64);
    for (int i = start; i < end; ++i) {
        int gq = idx_at(batch, i, is64);
        if (gq != gprev) {
            atomicAdd(&g_pool[gprev * DIM + t], acc);
            acc = 0.f;
            gprev = gq;
        }
        acc += __half2float(h[(size_t)i * 128 + t]);
    }
    atomicAdd(&g_pool[gprev * DIM + t], acc);
}

__global__ void k_final(const float* __restrict__ Wc, const float* __restrict__ bc,
                        float* __restrict__ out) {
    __shared__ float gs[DIM];
    int b = blockIdx.x, t = threadIdx.x;
    float c = fmaxf(g_cnt[b], 1.f);
    gs[t] = g_pool[b * DIM + t] / c;
    __syncthreads();
    if (t < NC) {
        float s = bc[t];
#pragma unroll 16
        for (int k = 0; k < DIM; ++k) s += gs[k] * Wc[k * NC + t];
        out[b * NC + t] = s;
    }
}

// ---------------- launch -------------------------------------------------------
extern "C" void kernel_launch(void* const* d_in, const int* in_sizes, int n_in,
                              void* d_out, int out_size) {
    const float* x     = (const float*)d_in[0];
    const void*  ei    = d_in[1];
    const void*  batch = d_in[2];
    const float* W1    = (const float*)d_in[3];
    const float* b1    = (const float*)d_in[4];
    const float* W2    = (const float*)d_in[5];
    const float* b2    = (const float*)d_in[6];
    const float* Wc    = (const float*)d_in[7];
    const float* bc    = (const float*)d_in[8];
    float*       out   = (float*)d_out;

    cudaFuncSetAttribute(k_gemm_tc, cudaFuncAttributeMaxDynamicSharedMemorySize, GEMM_SMEM);

    int gemm_blocks = (NN + 63) / 64;
    int agg_blocks = (NN * 32 + 255) / 256;

    k_zero<<<256, 256>>>(ei);                                     // 0 (incl. probe)
    k_wprep<<<64, 256>>>(W1, W2);                                 // 1
    k_hist<<<512, 256>>>(ei, batch);                              // 2
    k_gemm_tc<<<gemm_blocks, 512, GEMM_SMEM>>>(x, 0, 0, NN);      // 3 <- profiled
    k_scan_local<<<NBLK, SCAN_B>>>();                             // 4
    k_scan_blocks<<<1, 128>>>();                                  // 5
    k_scan_add<<<(NN + 255) / 256, 256>>>();                      // 6
    k_csr<<<512, 256>>>(ei);                                      // 7
    k_agg<<<agg_blocks, 256>>>(b1, 1);                            // 8
    k_gemm_tc<<<gemm_blocks, 512, GEMM_SMEM>>>(nullptr, 1, 1, NN);// 9
    k_agg<<<agg_blocks, 256>>>(b2, 0);                            // 10
    k_pool<<<(NN + PNODES - 1) / PNODES, DIM>>>(batch);           // 11
    k_final<<<NG, DIM>>>(Wc, bc, out);                            // 12
}

// round 13
// speedup vs baseline: 1.8603x; 1.0089x over previous
#include <cuda_runtime.h>
#include <cuda_bf16.h>
#include <cuda_fp16.h>
#include <cstdint>

#define NN 100000
#define NE 1600000
#define NG 512
#define DIM 128
#define NC 10
#define SCAN_B 1024
#define NBLK ((NN + SCAN_B - 1) / SCAN_B)

// ---------------- scratch (device globals) ------------------------------------
__device__ int            g_is64;
__device__ int            g_deg[NN];
__device__ float          g_dinv[NN];
__device__ int            g_off[NN + 1];
__device__ int            g_pos[NN];
__device__ int            g_src[NE];
__device__ int            g_bsum[NBLK];
__device__ __half2        g_xw16[(size_t)NN * 64];   // GEMM output, fp16 (gathered)
__device__ __half2        g_h16[(size_t)NN * 64];    // agg output, fp16
__device__ float          g_pool[NG * DIM];
__device__ float          g_cnt[NG];
__device__ unsigned short g_wb[2][2][16384];  // [layer][hi/lo][n*128+k]  B=W^T fp16

__device__ __forceinline__ int idx_at(const void* p, long long i, int is64) {
    return is64 ? (int)((const long long*)p)[i] : ((const int*)p)[i];
}
__device__ __forceinline__ unsigned short f16bits(float v) {
    __half h = __float2half_rn(v);
    return *reinterpret_cast<unsigned short*>(&h);
}
__device__ __forceinline__ float f16val(float v) {
    return __half2float(__float2half_rn(v));
}
__device__ __forceinline__ uint32_t h2u(__half2 h) {
    return *reinterpret_cast<uint32_t*>(&h);
}
__device__ __forceinline__ uint32_t smem_u32(const void* p) {
    uint32_t a;
    asm("{ .reg .u64 t; cvta.to.shared.u64 t, %1; cvt.u32.u64 %0, t; }" : "=r"(a) : "l"(p));
    return a;
}

#define LDSM4(r0, r1, r2, r3, addr)                                         \
    asm volatile("ldmatrix.sync.aligned.m8n8.x4.shared.b16 {%0,%1,%2,%3}, [%4];" \
                 : "=r"(r0), "=r"(r1), "=r"(r2), "=r"(r3) : "r"(addr))

#define MMA_F16(d, a0, a1, a2, a3, b0, b1)                                   \
    asm volatile("mma.sync.aligned.m16n8k16.row.col.f32.f16.f16.f32 "        \
                 "{%0,%1,%2,%3},{%4,%5,%6,%7},{%8,%9},{%0,%1,%2,%3};"        \
                 : "+f"(d[0]), "+f"(d[1]), "+f"(d[2]), "+f"(d[3])            \
                 : "r"(a0), "r"(a1), "r"(a2), "r"(a3), "r"(b0), "r"(b1))

// ---------------- setup (zero + dtype probe merged) ----------------------------
__global__ void k_zero(const void* ei) {
    if (blockIdx.x == 0 && threadIdx.x == 0) {
        const int* w = (const int*)ei;
        int nz = 0;
        for (int i = 0; i < 128; ++i) nz += (w[2 * i + 1] != 0);
        g_is64 = (nz == 0) ? 1 : 0;
    }
    int i = blockIdx.x * blockDim.x + threadIdx.x;
    int stride = gridDim.x * blockDim.x;
    for (int j = i; j < NN; j += stride) g_deg[j] = 0;
    for (int j = i; j < NG * DIM; j += stride) g_pool[j] = 0.f;
    for (int j = i; j < NG; j += stride) g_cnt[j] = 0.f;
}

// W[k][n] -> B[n][k] fp16 hi/lo for both layers
__global__ void k_wprep(const float* __restrict__ W1, const float* __restrict__ W2) {
    int i = blockIdx.x * blockDim.x + threadIdx.x;
    int stride = gridDim.x * blockDim.x;
    for (int e = i; e < 2 * 16384; e += stride) {
        int l = e >> 14;
        int idx = e & 16383;
        int nrow = idx >> 7, k = idx & 127;
        const float* W = l ? W2 : W1;
        float v = W[k * 128 + nrow];
        float hi = f16val(v);
        g_wb[l][0][idx] = f16bits(v);
        g_wb[l][1][idx] = f16bits(v - hi);
    }
}

__global__ void k_hist(const void* __restrict__ ei, const void* __restrict__ batch) {
    int i = blockIdx.x * blockDim.x + threadIdx.x;
    int stride = gridDim.x * blockDim.x;
    int is64 = g_is64;
    for (int e = i; e < NE; e += stride) {
        int d = idx_at(ei, (long long)NE + e, is64);
        atomicAdd(&g_deg[d], 1);
    }
    for (int j = i; j < NN; j += stride)
        atomicAdd(&g_cnt[idx_at(batch, j, is64)], 1.f);
}

__global__ void k_scan_local() {
    __shared__ int s[SCAN_B];
    int t = threadIdx.x;
    int idx = blockIdx.x * SCAN_B + t;
    int v = (idx < NN) ? g_deg[idx] : 0;
    if (idx < NN) g_dinv[idx] = rsqrtf((float)(v + 1));
    s[t] = v;
    __syncthreads();
    for (int d = 1; d < SCAN_B; d <<= 1) {
        int x = (t >= d) ? s[t - d] : 0;
        __syncthreads();
        s[t] += x;
        __syncthreads();
    }
    if (idx < NN) g_off[idx] = s[t] - v;
    if (t == SCAN_B - 1) g_bsum[blockIdx.x] = s[t];
}

// parallel exclusive scan of the block sums (single block)
__global__ void k_scan_blocks() {
    __shared__ int s[128];
    int t = threadIdx.x;
    int v = (t < NBLK) ? g_bsum[t] : 0;
    s[t] = v;
    __syncthreads();
    for (int d = 1; d < 128; d <<= 1) {
        int x = (t >= d) ? s[t - d] : 0;
        __syncthreads();
        s[t] += x;
        __syncthreads();
    }
    if (t < NBLK) g_bsum[t] = s[t] - v;   // exclusive
}

__global__ void k_scan_add() {
    int idx = blockIdx.x * blockDim.x + threadIdx.x;
    if (idx < NN) {
        int o = g_off[idx] + g_bsum[idx / SCAN_B];
        g_off[idx] = o;
        g_pos[idx] = o;
    }
    if (idx == 0) g_off[NN] = NE;
}

__global__ void k_csr(const void* __restrict__ ei) {
    int i = blockIdx.x * blockDim.x + threadIdx.x;
    int stride = gridDim.x * blockDim.x;
    int is64 = g_is64;
    for (int e = i; e < NE; e += stride) {
        int s = idx_at(ei, e, is64);
        int d = idx_at(ei, (long long)NE + e, is64);
        int p = atomicAdd(&g_pos[d], 1);
        g_src[p] = s;
    }
}

// ---------------- fp16 2-term tensor GEMM -> fp16 output ---------------------
// D = A(fp16) * (Wh + Wl).  64-row tiles, 512 threads (16 warps in 2x8 grid),
// warp tile = 32 rows x 16 cols, full K=128 resident. smem 85KB -> 2 CTAs/SM.
#define AST 136
#define SM_A  0
#define SM_WH 17408
#define SM_WL 52224
#define GEMM_SMEM 87040

__global__ __launch_bounds__(512, 2) void k_gemm_tc(const float* __restrict__ Aext,
                                                    int a_is_h16, int wsel, int n) {
    extern __shared__ char smem[];
    uint32_t sb = smem_u32(smem);
    int tid = threadIdx.x, wid = tid >> 5, lane = tid & 31;
    int row0 = blockIdx.x * 64;

    // ---- stage A (fp16): 64 rows x 128 k ----
    unsigned short* as = (unsigned short*)(smem + SM_A);
    if (a_is_h16) {
        for (int idx = tid; idx < 1024; idx += 512) {
            int row = idx >> 4;
            int ch = idx & 15;
            uint4 v = make_uint4(0, 0, 0, 0);
            if (row0 + row < n)
                v = ((const uint4*)g_h16)[(size_t)(row0 + row) * 16 + ch];
            *(uint4*)&as[row * AST + ch * 8] = v;
        }
    } else {
        for (int idx = tid; idx < 1024; idx += 512) {
            int row = idx >> 4;
            int ch = idx & 15;
            float4 v0 = make_float4(0.f, 0.f, 0.f, 0.f), v1 = v0;
            if (row0 + row < n) {
                const float* src = &Aext[(size_t)(row0 + row) * 128 + ch * 8];
                v0 = *(const float4*)src;
                v1 = *(const float4*)(src + 4);
            }
            uint4 o;
            o.x = h2u(__floats2half2_rn(v0.x, v0.y));
            o.y = h2u(__floats2half2_rn(v0.z, v0.w));
            o.z = h2u(__floats2half2_rn(v1.x, v1.y));
            o.w = h2u(__floats2half2_rn(v1.z, v1.w));
            *(uint4*)&as[row * AST + ch * 8] = o;
        }
    }
    // ---- stage W (full 128 n-rows x 128 k, both terms) ----
    {
        unsigned short* wh = (unsigned short*)(smem + SM_WH);
        unsigned short* wl = (unsigned short*)(smem + SM_WL);
        for (int idx = tid; idx < 2048; idx += 512) {
            int nr = idx >> 4;
            int kq = (idx & 15) * 8;
            *(uint4*)&wh[nr * AST + kq] = *(const uint4*)&g_wb[wsel][0][nr * 128 + kq];
            *(uint4*)&wl[nr * AST + kq] = *(const uint4*)&g_wb[wsel][1][nr * 128 + kq];
        }
    }
    __syncthreads();

    // ---- mainloop: warp = 32 rows x 16 cols ----
    float acc[4][4];
#pragma unroll
    for (int j = 0; j < 4; ++j)
#pragma unroll
        for (int q = 0; q < 4; ++q) acc[j][q] = 0.f;

    int wr = (wid >> 3) * 32;            // 0 or 32
    int wc = (wid & 7) * 16;             // 0..112
    uint32_t a_off = (uint32_t)(((wr + (lane & 15)) * AST + ((lane >> 4) << 3)) * 2);
    uint32_t b_off = (uint32_t)(((wc + (lane & 7) + ((lane >> 4) << 3)) * AST +
                                 (((lane >> 3) & 1) << 3)) * 2);
    uint32_t aA_addr = sb + SM_A + a_off;                  // rows wr..wr+15
    uint32_t aB_addr = aA_addr + 16 * AST * 2;             // rows wr+16..wr+31
    uint32_t bh_addr = sb + SM_WH + b_off;
    uint32_t bl_addr = sb + SM_WL + b_off;

#pragma unroll
    for (int p = 0; p < 8; ++p) {
        uint32_t ka = p * 32;
        uint32_t a0, a1, a2, a3, a4, a5, a6, a7;
        uint32_t bh0, bh1, bh2, bh3, bl0, bl1, bl2, bl3;
        LDSM4(a0, a1, a2, a3, aA_addr + ka);
        LDSM4(a4, a5, a6, a7, aB_addr + ka);
        LDSM4(bh0, bh1, bh2, bh3, bh_addr + ka);
        LDSM4(bl0, bl1, bl2, bl3, bl_addr + ka);
        MMA_F16(acc[0], a0, a1, a2, a3, bh0, bh1);
        MMA_F16(acc[1], a0, a1, a2, a3, bh2, bh3);
        MMA_F16(acc[2], a4, a5, a6, a7, bh0, bh1);
        MMA_F16(acc[3], a4, a5, a6, a7, bh2, bh3);
        MMA_F16(acc[0], a0, a1, a2, a3, bl0, bl1);
        MMA_F16(acc[1], a0, a1, a2, a3, bl2, bl3);
        MMA_F16(acc[2], a4, a5, a6, a7, bl0, bl1);
        MMA_F16(acc[3], a4, a5, a6, a7, bl2, bl3);
    }

    // ---- epilogue: fp16 stores ----
    // acc[0]: rows wr+(lane>>2)/+8,  cols wc+(lane&3)*2
    // acc[1]: same rows, cols +8 ; acc[2]/acc[3]: rows +16
    int rbase = row0 + wr + (lane >> 2);
    int cb = wc + (lane & 3) * 2;
#pragma unroll
    for (int half = 0; half < 2; ++half) {
        int r0 = rbase + half * 16;
#pragma unroll
        for (int j = 0; j < 2; ++j) {
            float* a = acc[half * 2 + j];
            int c = cb + j * 8;
            if (r0 < n)
                g_xw16[(size_t)r0 * 64 + (c >> 1)] = __floats2half2_rn(a[0], a[1]);
            if (r0 + 8 < n)
                g_xw16[(size_t)(r0 + 8) * 64 + (c >> 1)] = __floats2half2_rn(a[2], a[3]);
        }
    }
}

// ---------------- aggregation: one warp per destination node -----------------
// half-warp edge pairing: lanes 0-15 edge 2t, lanes 16-31 edge 2t+1,
// each lane loads uint4 (8 halves). fp32 accumulate, fp16 output.
__global__ void k_agg(const float* __restrict__ bias, int dorelu) {
    int warp = (blockIdx.x * blockDim.x + threadIdx.x) >> 5;
    if (warp >= NN) return;
    int lane = threadIdx.x & 31;
    int half = lane >> 4;
    int ch = lane & 15;
    float di = g_dinv[warp];
    const uint4* xw4 = (const uint4*)g_xw16;   // 16 uint4 per row

    float acc[8];
    {
        // self term: only half 0 (halves are summed at the end)
        uint4 r = xw4[(size_t)warp * 16 + ch];
        float w = half ? 0.f : di;
        float2 v0 = __half22float2(*(__half2*)&r.x);
        float2 v1 = __half22float2(*(__half2*)&r.y);
        float2 v2 = __half22float2(*(__half2*)&r.z);
        float2 v3 = __half22float2(*(__half2*)&r.w);
        acc[0] = v0.x * w; acc[1] = v0.y * w;
        acc[2] = v1.x * w; acc[3] = v1.y * w;
        acc[4] = v2.x * w; acc[5] = v2.y * w;
        acc[6] = v3.x * w; acc[7] = v3.y * w;
    }

    int e0 = g_off[warp], e1 = g_off[warp + 1];
    for (int e = e0; e < e1; e += 32) {
        int cnt = min(32, e1 - e);
        int sidx = (lane < cnt) ? g_src[e + lane] : 0;
        float dv = (lane < cnt) ? g_dinv[sidx] : 0.f;
        int iters = (cnt + 1) >> 1;
        for (int t = 0; t < iters; ++t) {
            int j = 2 * t + half;                       // <= 31; dv==0 past cnt
            int s = __shfl_sync(0xffffffffu, sidx, j);
            float w = __shfl_sync(0xffffffffu, dv, j);
            uint4 r = xw4[(size_t)s * 16 + ch];
            float2 v0 = __half22float2(*(__half2*)&r.x);
            float2 v1 = __half22float2(*(__half2*)&r.y);
            float2 v2 = __half22float2(*(__half2*)&r.z);
            float2 v3 = __half22float2(*(__half2*)&r.w);
            acc[0] += v0.x * w; acc[1] += v0.y * w;
            acc[2] += v1.x * w; acc[3] += v1.y * w;
            acc[4] += v2.x * w; acc[5] += v2.y * w;
            acc[6] += v3.x * w; acc[7] += v3.y * w;
        }
    }
    // merge half-warps
#pragma unroll
    for (int q = 0; q < 8; ++q)
        acc[q] += __shfl_xor_sync(0xffffffffu, acc[q], 16);

    if (half == 0) {
        float4 b0 = ((const float4*)bias)[ch * 2];
        float4 b1 = ((const float4*)bias)[ch * 2 + 1];
        acc[0] = acc[0] * di + b0.x;
        acc[1] = acc[1] * di + b0.y;
        acc[2] = acc[2] * di + b0.z;
        acc[3] = acc[3] * di + b0.w;
        acc[4] = acc[4] * di + b1.x;
        acc[5] = acc[5] * di + b1.y;
        acc[6] = acc[6] * di + b1.z;
        acc[7] = acc[7] * di + b1.w;
        if (dorelu) {
#pragma unroll
            for (int q = 0; q < 8; ++q) acc[q] = fmaxf(acc[q], 0.f);
        }
        uint4 o;
        o.x = h2u(__floats2half2_rn(acc[0], acc[1]));
        o.y = h2u(__floats2half2_rn(acc[2], acc[3]));
        o.z = h2u(__floats2half2_rn(acc[4], acc[5]));
        o.w = h2u(__floats2half2_rn(acc[6], acc[7]));
        ((uint4*)g_h16)[(size_t)warp * 16 + ch] = o;
    }
}

// ---------------- pooling ------------------------------------------------------
#define PNODES 256
__global__ void k_pool(const void* __restrict__ batch) {
    int t = threadIdx.x;
    int start = blockIdx.x * PNODES;
    int end = min(start + PNODES, NN);
    if (start >= NN) return;
    int is64 = g_is64;
    const __half* h = (const __half*)g_h16;
    float acc = 0.f;
    int gprev = idx_at(batch, start, is64);
    for (int i = start; i < end; ++i) {
        int gq = idx_at(batch, i, is64);
        if (gq != gprev) {
            atomicAdd(&g_pool[gprev * DIM + t], acc);
            acc = 0.f;
            gprev = gq;
        }
        acc += __half2float(h[(size_t)i * 128 + t]);
    }
    atomicAdd(&g_pool[gprev * DIM + t], acc);
}

__global__ void k_final(const float* __restrict__ Wc, const float* __restrict__ bc,
                        float* __restrict__ out) {
    __shared__ float gs[DIM];
    int b = blockIdx.x, t = threadIdx.x;
    float c = fmaxf(g_cnt[b], 1.f);
    gs[t] = g_pool[b * DIM + t] / c;
    __syncthreads();
    if (t < NC) {
        float s = bc[t];
#pragma unroll 16
        for (int k = 0; k < DIM; ++k) s += gs[k] * Wc[k * NC + t];
        out[b * NC + t] = s;
    }
}

// ---------------- launch -------------------------------------------------------
extern "C" void kernel_launch(void* const* d_in, const int* in_sizes, int n_in,
                              void* d_out, int out_size) {
    const float* x     = (const float*)d_in[0];
    const void*  ei    = d_in[1];
    const void*  batch = d_in[2];
    const float* W1    = (const float*)d_in[3];
    const float* b1    = (const float*)d_in[4];
    const float* W2    = (const float*)d_in[5];
    const float* b2    = (const float*)d_in[6];
    const float* Wc    = (const float*)d_in[7];
    const float* bc    = (const float*)d_in[8];
    float*       out   = (float*)d_out;

    cudaFuncSetAttribute(k_gemm_tc, cudaFuncAttributeMaxDynamicSharedMemorySize, GEMM_SMEM);

    int gemm_blocks = (NN + 63) / 64;
    int agg_blocks = (NN * 32 + 255) / 256;

    k_zero<<<256, 256>>>(ei);                                     // 0 (incl. probe)
    k_wprep<<<64, 256>>>(W1, W2);                                 // 1
    k_hist<<<512, 256>>>(ei, batch);                              // 2
    k_gemm_tc<<<gemm_blocks, 512, GEMM_SMEM>>>(x, 0, 0, NN);      // 3 <- profiled
    k_scan_local<<<NBLK, SCAN_B>>>();                             // 4
    k_scan_blocks<<<1, 128>>>();                                  // 5
    k_scan_add<<<(NN + 255) / 256, 256>>>();                      // 6
    k_csr<<<512, 256>>>(ei);                                      // 7
    k_agg<<<agg_blocks, 256>>>(b1, 1);                            // 8
    k_gemm_tc<<<gemm_blocks, 512, GEMM_SMEM>>>(nullptr, 1, 1, NN);// 9
    k_agg<<<agg_blocks, 256>>>(b2, 0);                            // 10
    k_pool<<<(NN + PNODES - 1) / PNODES, DIM>>>(batch);           // 11
    k_final<<<NG, DIM>>>(Wc, bc, out);                            // 12
}

// round 14
// speedup vs baseline: 2.7180x; 1.4611x over previous
#include <cuda_runtime.h>
#include <cuda_bf16.h>
#include <cuda_fp16.h>
#include <cstdint>

#define NN 100000
#define NE 1600000
#define NG 512
#define DIM 128
#define NC 10

// ---------------- scratch (device globals) ------------------------------------
__device__ int            g_is64;
__device__ int            g_total;
__device__ int            g_deg[NN];
__device__ float          g_dinv[NN];
__device__ int            g_off[NN];
__device__ int            g_pos[NN];
__device__ int            g_src[NE];
__device__ __half2        g_xw16[(size_t)NN * 64];   // GEMM output, fp16 (gathered)
__device__ __half2        g_h16[(size_t)NN * 64];    // agg output, fp16
__device__ unsigned short g_wb[2][16384];            // [layer][n*128+k]  B=W^T fp16

__device__ __forceinline__ int idx_at(const void* p, long long i, int is64) {
    return is64 ? (int)((const long long*)p)[i] : ((const int*)p)[i];
}
__device__ __forceinline__ unsigned short f16bits(float v) {
    __half h = __float2half_rn(v);
    return *reinterpret_cast<unsigned short*>(&h);
}
__device__ __forceinline__ uint32_t h2u(__half2 h) {
    return *reinterpret_cast<uint32_t*>(&h);
}
__device__ __forceinline__ uint32_t smem_u32(const void* p) {
    uint32_t a;
    asm("{ .reg .u64 t; cvta.to.shared.u64 t, %1; cvt.u32.u64 %0, t; }" : "=r"(a) : "l"(p));
    return a;
}

#define LDSM4(r0, r1, r2, r3, addr)                                         \
    asm volatile("ldmatrix.sync.aligned.m8n8.x4.shared.b16 {%0,%1,%2,%3}, [%4];" \
                 : "=r"(r0), "=r"(r1), "=r"(r2), "=r"(r3) : "r"(addr))

#define MMA_F16(d, a0, a1, a2, a3, b0, b1)                                   \
    asm volatile("mma.sync.aligned.m16n8k16.row.col.f32.f16.f16.f32 "        \
                 "{%0,%1,%2,%3},{%4,%5,%6,%7},{%8,%9},{%0,%1,%2,%3};"        \
                 : "+f"(d[0]), "+f"(d[1]), "+f"(d[2]), "+f"(d[3])            \
                 : "r"(a0), "r"(a1), "r"(a2), "r"(a3), "r"(b0), "r"(b1))

// ---------------- setup (zero + dtype probe) ----------------------------------
__global__ void k_zero(const void* ei) {
    if (blockIdx.x == 0 && threadIdx.x == 0) {
        const int* w = (const int*)ei;
        int nz = 0;
        for (int i = 0; i < 128; ++i) nz += (w[2 * i + 1] != 0);
        g_is64 = (nz == 0) ? 1 : 0;
        g_total = 0;
    }
    int i = blockIdx.x * blockDim.x + threadIdx.x;
    int stride = gridDim.x * blockDim.x;
    for (int j = i; j < NN; j += stride) g_deg[j] = 0;
}

// W[k][n] -> B[n][k] fp16 for both layers
__global__ void k_wprep(const float* __restrict__ W1, const float* __restrict__ W2) {
    int i = blockIdx.x * blockDim.x + threadIdx.x;
    int stride = gridDim.x * blockDim.x;
    for (int e = i; e < 2 * 16384; e += stride) {
        int l = e >> 14;
        int idx = e & 16383;
        int nrow = idx >> 7, k = idx & 127;
        const float* W = l ? W2 : W1;
        g_wb[l][idx] = f16bits(W[k * 128 + nrow]);
    }
}

__global__ void k_hist(const void* __restrict__ ei) {
    int i = blockIdx.x * blockDim.x + threadIdx.x;
    int stride = gridDim.x * blockDim.x;
    int is64 = g_is64;
    for (int e = i; e < NE; e += stride) {
        int d = idx_at(ei, (long long)NE + e, is64);
        atomicAdd(&g_deg[d], 1);
    }
}

// segment allocation: warp-scan degrees, one atomic per warp; also dinv
__global__ void k_alloc() {
    int i = blockIdx.x * blockDim.x + threadIdx.x;
    int lane = threadIdx.x & 31;
    int deg = (i < NN) ? g_deg[i] : 0;
    if (i < NN) g_dinv[i] = rsqrtf((float)(deg + 1));
    int x = deg;
#pragma unroll
    for (int d = 1; d < 32; d <<= 1) {
        int y = __shfl_up_sync(0xffffffffu, x, d);
        if (lane >= d) x += y;
    }
    int warpsum = __shfl_sync(0xffffffffu, x, 31);
    int base = 0;
    if (lane == 31) base = atomicAdd(&g_total, warpsum);
    base = __shfl_sync(0xffffffffu, base, 31);
    int start = base + x - deg;
    if (i < NN) {
        g_off[i] = start;
        g_pos[i] = start;
    }
}

__global__ void k_csr(const void* __restrict__ ei) {
    int i = blockIdx.x * blockDim.x + threadIdx.x;
    int stride = gridDim.x * blockDim.x;
    int is64 = g_is64;
    for (int e = i; e < NE; e += stride) {
        int s = idx_at(ei, e, is64);
        int d = idx_at(ei, (long long)NE + e, is64);
        int p = atomicAdd(&g_pos[d], 1);
        g_src[p] = s;
    }
}

// ---------------- fp16 tensor GEMM -> fp16 output ----------------------------
// D = A(fp16) * W(fp16).  64-row tiles, 512 threads (16 warps in 2x8 grid),
// warp tile = 32 rows x 16 cols, full K=128 resident. smem 52KB -> 4 CTAs/SM.
#define AST 136
#define SM_A  0
#define SM_W  17408
#define GEMM_SMEM 52224

__global__ __launch_bounds__(512, 4) void k_gemm_tc(const float* __restrict__ Aext,
                                                    int a_is_h16, int wsel, int n) {
    extern __shared__ char smem[];
    uint32_t sb = smem_u32(smem);
    int tid = threadIdx.x, wid = tid >> 5, lane = tid & 31;
    int row0 = blockIdx.x * 64;

    // ---- stage A (fp16): 64 rows x 128 k ----
    unsigned short* as = (unsigned short*)(smem + SM_A);
    if (a_is_h16) {
        for (int idx = tid; idx < 1024; idx += 512) {
            int row = idx >> 4;
            int ch = idx & 15;
            uint4 v = make_uint4(0, 0, 0, 0);
            if (row0 + row < n)
                v = ((const uint4*)g_h16)[(size_t)(row0 + row) * 16 + ch];
            *(uint4*)&as[row * AST + ch * 8] = v;
        }
    } else {
        for (int idx = tid; idx < 1024; idx += 512) {
            int row = idx >> 4;
            int ch = idx & 15;
            float4 v0 = make_float4(0.f, 0.f, 0.f, 0.f), v1 = v0;
            if (row0 + row < n) {
                const float* src = &Aext[(size_t)(row0 + row) * 128 + ch * 8];
                v0 = *(const float4*)src;
                v1 = *(const float4*)(src + 4);
            }
            uint4 o;
            o.x = h2u(__floats2half2_rn(v0.x, v0.y));
            o.y = h2u(__floats2half2_rn(v0.z, v0.w));
            o.z = h2u(__floats2half2_rn(v1.x, v1.y));
            o.w = h2u(__floats2half2_rn(v1.z, v1.w));
            *(uint4*)&as[row * AST + ch * 8] = o;
        }
    }
    // ---- stage W (128 n-rows x 128 k) ----
    {
        unsigned short* ws = (unsigned short*)(smem + SM_W);
        for (int idx = tid; idx < 2048; idx += 512) {
            int nr = idx >> 4;
            int kq = (idx & 15) * 8;
            *(uint4*)&ws[nr * AST + kq] = *(const uint4*)&g_wb[wsel][nr * 128 + kq];
        }
    }
    __syncthreads();

    // ---- mainloop: warp = 32 rows x 16 cols ----
    float acc[4][4];
#pragma unroll
    for (int j = 0; j < 4; ++j)
#pragma unroll
        for (int q = 0; q < 4; ++q) acc[j][q] = 0.f;

    int wr = (wid >> 3) * 32;            // 0 or 32
    int wc = (wid & 7) * 16;             // 0..112
    uint32_t a_off = (uint32_t)(((wr + (lane & 15)) * AST + ((lane >> 4) << 3)) * 2);
    uint32_t b_off = (uint32_t)(((wc + (lane & 7) + ((lane >> 4) << 3)) * AST +
                                 (((lane >> 3) & 1) << 3)) * 2);
    uint32_t aA_addr = sb + SM_A + a_off;
    uint32_t aB_addr = aA_addr + 16 * AST * 2;
    uint32_t b_addr  = sb + SM_W + b_off;

#pragma unroll
    for (int p = 0; p < 8; ++p) {
        uint32_t ka = p * 32;
        uint32_t a0, a1, a2, a3, a4, a5, a6, a7;
        uint32_t b0, b1, b2, b3;
        LDSM4(a0, a1, a2, a3, aA_addr + ka);
        LDSM4(a4, a5, a6, a7, aB_addr + ka);
        LDSM4(b0, b1, b2, b3, b_addr + ka);
        MMA_F16(acc[0], a0, a1, a2, a3, b0, b1);
        MMA_F16(acc[1], a0, a1, a2, a3, b2, b3);
        MMA_F16(acc[2], a4, a5, a6, a7, b0, b1);
        MMA_F16(acc[3], a4, a5, a6, a7, b2, b3);
    }

    // ---- epilogue: fp16 stores ----
    int rbase = row0 + wr + (lane >> 2);
    int cb = wc + (lane & 3) * 2;
#pragma unroll
    for (int half = 0; half < 2; ++half) {
        int r0 = rbase + half * 16;
#pragma unroll
        for (int j = 0; j < 2; ++j) {
            float* a = acc[half * 2 + j];
            int c = cb + j * 8;
            if (r0 < n)
                g_xw16[(size_t)r0 * 64 + (c >> 1)] = __floats2half2_rn(a[0], a[1]);
            if (r0 + 8 < n)
                g_xw16[(size_t)(r0 + 8) * 64 + (c >> 1)] = __floats2half2_rn(a[2], a[3]);
        }
    }
}

// ---------------- aggregation: one warp per destination node (R12 form) ------
__global__ void k_agg(const float* __restrict__ bias, int dorelu) {
    int warp = (blockIdx.x * blockDim.x + threadIdx.x) >> 5;
    if (warp >= NN) return;
    int lane = threadIdx.x & 31;
    float di = g_dinv[warp];
    const uint2* xw2 = (const uint2*)g_xw16;

    uint2 raw = xw2[(size_t)warp * 32 + lane];
    float2 f0 = __half22float2(*(__half2*)&raw.x);
    float2 f1 = __half22float2(*(__half2*)&raw.y);
    float4 acc = make_float4(f0.x * di, f0.y * di, f1.x * di, f1.y * di);

    int e0 = g_off[warp], e1 = e0 + g_deg[warp];
    for (int e = e0; e < e1; e += 32) {
        int cnt = min(32, e1 - e);
        int sidx = (lane < cnt) ? g_src[e + lane] : 0;
        float dv = (lane < cnt) ? g_dinv[sidx] : 0.f;
#pragma unroll 4
        for (int j = 0; j < cnt; ++j) {
            int s = __shfl_sync(0xffffffffu, sidx, j);
            float w = __shfl_sync(0xffffffffu, dv, j);
            uint2 r = xw2[(size_t)s * 32 + lane];
            float2 v0 = __half22float2(*(__half2*)&r.x);
            float2 v1 = __half22float2(*(__half2*)&r.y);
            acc.x += v0.x * w;
            acc.y += v0.y * w;
            acc.z += v1.x * w;
            acc.w += v1.y * w;
        }
    }
    float4 bb = ((const float4*)bias)[lane];
    acc.x = acc.x * di + bb.x;
    acc.y = acc.y * di + bb.y;
    acc.z = acc.z * di + bb.z;
    acc.w = acc.w * di + bb.w;
    if (dorelu) {
        acc.x = fmaxf(acc.x, 0.f);
        acc.y = fmaxf(acc.y, 0.f);
        acc.z = fmaxf(acc.z, 0.f);
        acc.w = fmaxf(acc.w, 0.f);
    }
    uint2 o;
    o.x = h2u(__floats2half2_rn(acc.x, acc.y));
    o.y = h2u(__floats2half2_rn(acc.z, acc.w));
    ((uint2*)g_h16)[(size_t)warp * 32 + lane] = o;
}

// ---------------- fused pool + classifier (batch is sorted) -------------------
__global__ void k_final(const void* __restrict__ batch, const float* __restrict__ Wc,
                        const float* __restrict__ bc, float* __restrict__ out) {
    __shared__ float gs[DIM];
    __shared__ int srange[2];
    int b = blockIdx.x, t = threadIdx.x;
    int is64 = g_is64;
    if (t < 2) {
        int target = b + t;     // lower_bound of target
        int lo = 0, hi = NN;
        while (lo < hi) {
            int m = (lo + hi) >> 1;
            if (idx_at(batch, m, is64) < target) lo = m + 1;
            else hi = m;
        }
        srange[t] = lo;
    }
    __syncthreads();
    int lo = srange[0], hi = srange[1];
    const __half* h = (const __half*)g_h16;
    float acc = 0.f;
    for (int i = lo; i < hi; ++i)
        acc += __half2float(h[(size_t)i * 128 + t]);
    float c = fmaxf((float)(hi - lo), 1.f);
    gs[t] = acc / c;
    __syncthreads();
    if (t < NC) {
        float s = bc[t];
#pragma unroll 16
        for (int k = 0; k < DIM; ++k) s += gs[k] * Wc[k * NC + t];
        out[b * NC + t] = s;
    }
}

// ---------------- launch -------------------------------------------------------
extern "C" void kernel_launch(void* const* d_in, const int* in_sizes, int n_in,
                              void* d_out, int out_size) {
    const float* x     = (const float*)d_in[0];
    const void*  ei    = d_in[1];
    const void*  batch = d_in[2];
    const float* W1    = (const float*)d_in[3];
    const float* b1    = (const float*)d_in[4];
    const float* W2    = (const float*)d_in[5];
    const float* b2    = (const float*)d_in[6];
    const float* Wc    = (const float*)d_in[7];
    const float* bc    = (const float*)d_in[8];
    float*       out   = (float*)d_out;

    cudaFuncSetAttribute(k_gemm_tc, cudaFuncAttributeMaxDynamicSharedMemorySize, GEMM_SMEM);

    int gemm_blocks = (NN + 63) / 64;
    int agg_blocks = (NN * 32 + 255) / 256;

    k_zero<<<256, 256>>>(ei);                                      // 0 (incl. probe)
    k_wprep<<<64, 256>>>(W1, W2);                                  // 1
    k_hist<<<512, 256>>>(ei);                                      // 2
    k_gemm_tc<<<gemm_blocks, 512, GEMM_SMEM>>>(x, 0, 0, NN);       // 3 <- profiled
    k_alloc<<<(NN + 255) / 256, 256>>>();                          // 4
    k_csr<<<512, 256>>>(ei);                                       // 5
    k_agg<<<agg_blocks, 256>>>(b1, 1);                             // 6
    k_gemm_tc<<<gemm_blocks, 512, GEMM_SMEM>>>(nullptr, 1, 1, NN); // 7
    k_agg<<<agg_blocks, 256>>>(b2, 0);                             // 8
    k_final<<<NG, DIM>>>(batch, Wc, bc, out);                      // 9
}